// round 14
// baseline (speedup 1.0000x reference)
#include <cuda_runtime.h>
#include <cuda_fp16.h>
#include <math.h>
#include <stdint.h>

#define BB   2
#define NN   2048
#define LL   2048
#define DQ   1024
#define HH   16
#define HD   64
#define MROWS 4096
#define DFF  4096
#define LOG2E 1.4426950408889634f

typedef __half hf;

// ---------------------------------------------------------------------------
// Static scratch (fp16), offsets in EM elements.
// ---------------------------------------------------------------------------
#define EM (1024u*1024u)
__device__ __align__(256) hf g_hf[60u * EM];

#define O_XQ  0
#define O_XKV 4
#define O_ATT 8
#define O_X2  12
#define O_H   16
#define O_WQ  32
#define O_WK  33
#define O_WV  34
#define O_WO  35
#define O_W1  36
#define O_W2  40
#define O_Q   44
#define O_K   48
#define O_V   52

// ---------------------------------------------------------------------------
// helpers
// ---------------------------------------------------------------------------
__device__ __forceinline__ uint32_t smem_u32(const void* p) {
    uint32_t a;
    asm("{ .reg .u64 t; cvta.to.shared.u64 t, %1; cvt.u32.u64 %0, t; }" : "=r"(a) : "l"(p));
    return a;
}
__device__ __forceinline__ void ldmx4(uint32_t& r0, uint32_t& r1, uint32_t& r2,
                                      uint32_t& r3, uint32_t a) {
    asm volatile("ldmatrix.sync.aligned.m8n8.x4.shared.b16 {%0,%1,%2,%3}, [%4];"
                 : "=r"(r0), "=r"(r1), "=r"(r2), "=r"(r3) : "r"(a));
}
__device__ __forceinline__ void ldmx2(uint32_t& r0, uint32_t& r1, uint32_t a) {
    asm volatile("ldmatrix.sync.aligned.m8n8.x2.shared.b16 {%0,%1}, [%2];"
                 : "=r"(r0), "=r"(r1) : "r"(a));
}
__device__ __forceinline__ void ldmx2t(uint32_t& r0, uint32_t& r1, uint32_t a) {
    asm volatile("ldmatrix.sync.aligned.m8n8.x2.trans.shared.b16 {%0,%1}, [%2];"
                 : "=r"(r0), "=r"(r1) : "r"(a));
}
__device__ __forceinline__ void mma16816(float* d, const uint32_t* a,
                                         uint32_t b0, uint32_t b1) {
    asm volatile(
        "mma.sync.aligned.m16n8k16.row.col.f32.f16.f16.f32 "
        "{%0,%1,%2,%3}, {%4,%5,%6,%7}, {%8,%9}, {%0,%1,%2,%3};"
        : "+f"(d[0]), "+f"(d[1]), "+f"(d[2]), "+f"(d[3])
        : "r"(a[0]), "r"(a[1]), "r"(a[2]), "r"(a[3]), "r"(b0), "r"(b1));
}
__device__ __forceinline__ void cp16(uint32_t dst, const void* src) {
    asm volatile("cp.async.cg.shared.global [%0], [%1], 16;" :: "r"(dst), "l"(src));
}
#define CP_COMMIT() asm volatile("cp.async.commit_group;" ::: "memory")
#define CP_WAIT0()  asm volatile("cp.async.wait_group 0;" ::: "memory")
#define CP_WAIT1()  asm volatile("cp.async.wait_group 1;" ::: "memory")

__device__ __forceinline__ float gelu_exact(float x) {
    return 0.5f * x * (1.f + erff(x * 0.7071067811865476f));
}
__device__ __forceinline__ uint32_t pack2(float a, float b) {
    __half2 H = __halves2half2(__float2half_rn(a), __float2half_rn(b));
    return *(uint32_t*)&H;
}

// GEMM smem swizzle: pitch 64B, 16B chunk XORed with (row>>1)&3.
__device__ __forceinline__ uint32_t swz(uint32_t row, uint32_t colbyte) {
    return row * 64 + ((((colbyte >> 4) ^ (row >> 1)) & 3u) << 4);
}

// ---------------------------------------------------------------------------
// Fused LayerNorm (two tensors) -> single fp16
// ---------------------------------------------------------------------------
__global__ void ln2x_kernel(const float* __restrict__ xA,
                            const float* __restrict__ gA,
                            const float* __restrict__ bA,
                            hf* __restrict__ yA,
                            const float* __restrict__ xB,
                            const float* __restrict__ gB,
                            const float* __restrict__ bB,
                            hf* __restrict__ yB) {
    int row = blockIdx.x;
    const float* x; const float* g; const float* b; hf* y;
    if (row < MROWS) { x = xA; g = gA; b = bA; y = yA; }
    else { x = xB; g = gB; b = bB; y = yB; row -= MROWS; }

    const float* xr = x + (size_t)row * DQ;
    float v[4];
    float s = 0.f, s2 = 0.f;
#pragma unroll
    for (int i = 0; i < 4; i++) {
        float t = xr[threadIdx.x + i * 256];
        v[i] = t; s += t; s2 += t * t;
    }
#pragma unroll
    for (int o = 16; o > 0; o >>= 1) {
        s  += __shfl_xor_sync(0xffffffffu, s,  o);
        s2 += __shfl_xor_sync(0xffffffffu, s2, o);
    }
    __shared__ float ws[8], ws2[8];
    int w = threadIdx.x >> 5, lane = threadIdx.x & 31;
    if (lane == 0) { ws[w] = s; ws2[w] = s2; }
    __syncthreads();
    if (w == 0) {
        s  = (lane < 8) ? ws[lane]  : 0.f;
        s2 = (lane < 8) ? ws2[lane] : 0.f;
#pragma unroll
        for (int o = 4; o > 0; o >>= 1) {
            s  += __shfl_xor_sync(0xffffffffu, s,  o);
            s2 += __shfl_xor_sync(0xffffffffu, s2, o);
        }
        if (lane == 0) { ws[0] = s; ws2[0] = s2; }
    }
    __syncthreads();
    float mean = ws[0] * (1.f / DQ);
    float var  = ws2[0] * (1.f / DQ) - mean * mean;
    float rstd = rsqrtf(var + 1e-5f);
    size_t base = (size_t)row * DQ;
#pragma unroll
    for (int i = 0; i < 4; i++) {
        int c = threadIdx.x + i * 256;
        float yv = (v[i] - mean) * rstd * g[c] + b[c];
        y[base + c] = __float2half_rn(yv);
    }
}

// single-tensor LN (for LN2)
__global__ void ln_kernel(const float* __restrict__ x,
                          const float* __restrict__ g,
                          const float* __restrict__ b,
                          hf* __restrict__ y) {
    int row = blockIdx.x;
    const float* xr = x + (size_t)row * DQ;
    float v[4];
    float s = 0.f, s2 = 0.f;
#pragma unroll
    for (int i = 0; i < 4; i++) {
        float t = xr[threadIdx.x + i * 256];
        v[i] = t; s += t; s2 += t * t;
    }
#pragma unroll
    for (int o = 16; o > 0; o >>= 1) {
        s  += __shfl_xor_sync(0xffffffffu, s,  o);
        s2 += __shfl_xor_sync(0xffffffffu, s2, o);
    }
    __shared__ float ws[8], ws2[8];
    int w = threadIdx.x >> 5, lane = threadIdx.x & 31;
    if (lane == 0) { ws[w] = s; ws2[w] = s2; }
    __syncthreads();
    if (w == 0) {
        s  = (lane < 8) ? ws[lane]  : 0.f;
        s2 = (lane < 8) ? ws2[lane] : 0.f;
#pragma unroll
        for (int o = 4; o > 0; o >>= 1) {
            s  += __shfl_xor_sync(0xffffffffu, s,  o);
            s2 += __shfl_xor_sync(0xffffffffu, s2, o);
        }
        if (lane == 0) { ws[0] = s; ws2[0] = s2; }
    }
    __syncthreads();
    float mean = ws[0] * (1.f / DQ);
    float var  = ws2[0] * (1.f / DQ) - mean * mean;
    float rstd = rsqrtf(var + 1e-5f);
    size_t base = (size_t)row * DQ;
#pragma unroll
    for (int i = 0; i < 4; i++) {
        int c = threadIdx.x + i * 256;
        float yv = (v[i] - mean) * rstd * g[c] + b[c];
        y[base + c] = __float2half_rn(yv);
    }
}

// ---------------------------------------------------------------------------
// Single fused weight convert: all 6 weights -> fp16. 3M float4 entries.
// ---------------------------------------------------------------------------
__global__ void convert_all_kernel(
    const float* __restrict__ wq, const float* __restrict__ wk,
    const float* __restrict__ wv, const float* __restrict__ wo,
    const float* __restrict__ w1, const float* __restrict__ w2,
    hf* __restrict__ base) {
    int i = blockIdx.x * blockDim.x + threadIdx.x;   // 0 .. 3M-1
    const float* w; hf* h; int off;
    if (i < (1 << 20)) {
        int seg = i >> 18;
        off = i & 0x3FFFF;
        w = seg == 0 ? wq : seg == 1 ? wk : seg == 2 ? wv : wo;
        h = base + (size_t)(O_WQ + seg) * EM;
    } else {
        int j = i - (1 << 20);
        int seg = j >> 20;
        off = j & 0xFFFFF;
        w = seg == 0 ? w1 : w2;
        h = base + (size_t)(seg == 0 ? O_W1 : O_W2) * EM;
    }
    float4 v = ((const float4*)w)[off];
    __half2* hp = (__half2*)(h + (size_t)off * 4);
    hp[0] = __halves2half2(__float2half_rn(v.x), __float2half_rn(v.y));
    hp[1] = __halves2half2(__float2half_rn(v.z), __float2half_rn(v.w));
}

// ---------------------------------------------------------------------------
// HMMA GEMM core: fp16 operands, fp32 accumulate.
// 128 threads, 4 warps, CTA tile 128x128, warp tile 64x64 (4 MMA / LDSM).
// 3-stage cp.async pipeline, pitch-64 XOR swizzle.
// EPI: 1 bias+res->fp32; 2 gelu->fp16; 3 bias+C rmw; 5 (acc+bias)*alpha->fp16
// ---------------------------------------------------------------------------
#define MAT_BYTES (128 * 64)
#define STAGE_BYTES (2 * MAT_BYTES)   // 16384
#define GEMM_SMEM (3 * STAGE_BYTES)   // 49152

template <int EPI>
__device__ __forceinline__ void gemm_core(
    const hf* __restrict__ A, const hf* __restrict__ B,
    const float* __restrict__ bias, const float* __restrict__ res,
    float* __restrict__ C, hf* __restrict__ Ho,
    int N, int K, float alpha, size_t m0, size_t n0, char* smc) {
    const int tid = threadIdx.x, lane = tid & 31, wid = tid >> 5;  // 0..3
    const int wm = wid & 1, wn = wid >> 1;                          // 0..1
    const uint32_t sbase = smem_u32(smc);

    const hf* gsrc0 = A + m0 * K;
    const hf* gsrc1 = B + n0 * K;

    auto load_stage = [&](int s, int kt) {
        uint32_t base = sbase + s * STAGE_BYTES;
#pragma unroll
        for (int i = 0; i < 8; i++) {
            int g = i * 128 + tid;             // 0..1023
            int t = g >> 9;                    // 0 A, 1 B
            int row = (g & 511) >> 2, seg = g & 3;
            const hf* src = (t == 0 ? gsrc0 : gsrc1);
            cp16(base + t * MAT_BYTES + swz((uint32_t)row, (uint32_t)(seg * 16)),
                 src + (size_t)row * K + kt + seg * 8);
        }
    };

    float acc[4][8][4];
#pragma unroll
    for (int a = 0; a < 4; a++)
#pragma unroll
        for (int b = 0; b < 8; b++)
#pragma unroll
            for (int c = 0; c < 4; c++) acc[a][b][c] = 0.f;

    const int nk = K >> 5;
    load_stage(0, 0);
    CP_COMMIT();
    load_stage(1, 32);
    CP_COMMIT();

    const uint32_t brow = (uint32_t)(wn * 64 + ((lane >> 4) & 1) * 8 + (lane & 7));
    const uint32_t bcolh = (uint32_t)(((lane >> 3) & 1) * 16);
    const uint32_t arow = (uint32_t)(wm * 64 + (lane & 15));
    const uint32_t acolh = (uint32_t)((lane >> 4) * 16);

    int stage = 0;
    for (int cc = 0; cc < nk; cc++) {
        if (cc + 1 < nk) CP_WAIT1(); else CP_WAIT0();
        __syncthreads();
        if (cc + 2 < nk) {
            int ns = stage + 2; if (ns >= 3) ns -= 3;
            load_stage(ns, (cc + 2) << 5);
            CP_COMMIT();
        }

        uint32_t st = sbase + stage * STAGE_BYTES;
        uint32_t sA = st, sB = st + MAT_BYTES;

#pragma unroll
        for (int k16 = 0; k16 < 2; k16++) {
            // B fragments for 8 nt (4 ldmx4)
            uint32_t Bv[16];
            uint32_t bcol = (uint32_t)(k16 * 32) + bcolh;
#pragma unroll
            for (int pr = 0; pr < 4; pr++) {
                uint32_t bo = swz(brow + pr * 16, bcol);
                ldmx4(Bv[pr * 4 + 0], Bv[pr * 4 + 1],
                      Bv[pr * 4 + 2], Bv[pr * 4 + 3], sB + bo);
            }
#pragma unroll
            for (int mt = 0; mt < 4; mt++) {
                uint32_t ao = swz(arow + mt * 16, (uint32_t)(k16 * 32) + acolh);
                uint32_t av[4];
                ldmx4(av[0], av[1], av[2], av[3], sA + ao);
#pragma unroll
                for (int nt = 0; nt < 8; nt++)
                    mma16816(acc[mt][nt], av, Bv[nt * 2], Bv[nt * 2 + 1]);
            }
        }
        stage++; if (stage >= 3) stage -= 3;
    }

#pragma unroll
    for (int mt = 0; mt < 4; mt++) {
        int r0 = wm * 64 + mt * 16 + (lane >> 2);
#pragma unroll
        for (int nt = 0; nt < 8; nt++) {
            size_t gcol = n0 + wn * 64 + nt * 8 + (lane & 3) * 2;
            float2 bb = *(const float2*)(bias + gcol);
#pragma unroll
            for (int h = 0; h < 2; h++) {
                size_t grow = m0 + r0 + h * 8;
                size_t idx = grow * (size_t)N + gcol;
                float v0 = acc[mt][nt][h * 2 + 0] + bb.x;
                float v1 = acc[mt][nt][h * 2 + 1] + bb.y;
                if (EPI == 1) {
                    float2 rr = *(const float2*)(res + idx);
                    v0 += rr.x; v1 += rr.y;
                }
                if (EPI == 3) {
                    float2 rr = *(const float2*)(C + idx);
                    v0 += rr.x; v1 += rr.y;
                }
                if (EPI == 2) {
                    v0 = gelu_exact(v0); v1 = gelu_exact(v1);
                    *(__half2*)(Ho + idx) =
                        __halves2half2(__float2half_rn(v0), __float2half_rn(v1));
                } else if (EPI == 5) {
                    v0 *= alpha; v1 *= alpha;
                    *(__half2*)(Ho + idx) =
                        __halves2half2(__float2half_rn(v0), __float2half_rn(v1));
                } else {
                    float2 o; o.x = v0; o.y = v1;
                    *(float2*)(C + idx) = o;
                }
            }
        }
    }
}

template <int EPI>
__global__ void __launch_bounds__(128, 3)
gemm_mma(const hf* __restrict__ A, const hf* __restrict__ B,
         const float* __restrict__ bias, const float* __restrict__ res,
         float* __restrict__ C, hf* __restrict__ Ho,
         int N, int K, float alpha) {
    extern __shared__ char smc[];
    gemm_core<EPI>(A, B, bias, res, C, Ho, N, K, alpha,
                   (size_t)blockIdx.y * 128, (size_t)blockIdx.x * 128, smc);
}

// Fused Q/K/V projection
__global__ void __launch_bounds__(128, 3)
gemm_qkv(const hf* __restrict__ XQ, const hf* __restrict__ XKV,
         const hf* __restrict__ WQ, const hf* __restrict__ WK,
         const hf* __restrict__ WV,
         const float* __restrict__ bq, const float* __restrict__ bk,
         const float* __restrict__ bv,
         hf* __restrict__ Q, hf* __restrict__ K, hf* __restrict__ V) {
    extern __shared__ char smc[];
    size_t m0 = (size_t)blockIdx.y * 128;
    int xb = blockIdx.x;
    if (xb < 8) {
        // fold softmax scale AND log2(e) into Q so attention uses exp2
        gemm_core<5>(XQ, WQ, bq, nullptr, nullptr, Q,
                     DQ, DQ, 0.125f * LOG2E, m0, (size_t)xb * 128, smc);
    } else if (xb < 16) {
        gemm_core<5>(XKV, WK, bk, nullptr, nullptr, K,
                     DQ, DQ, 1.0f, m0, (size_t)(xb - 8) * 128, smc);
    } else {
        gemm_core<5>(XKV, WV, bv, nullptr, nullptr, V,
                     DQ, DQ, 1.0f, m0, (size_t)(xb - 16) * 128, smc);
    }
}

// ---------------------------------------------------------------------------
// Tensor-core flash attention, softmax-1 in log2 domain (Q pre-scaled).
// 128 threads x 64 q-rows, 4 CTAs/SM.
// ---------------------------------------------------------------------------
#define APB 144
#define KV_MAT (64 * APB)            // 9216
#define KV_STAGE (2 * KV_MAT)        // 18432
#define ATTN_SMEM (2 * KV_STAGE)     // 36864

__global__ void __launch_bounds__(128, 4)
attn_mma(const hf* __restrict__ Qp, const hf* __restrict__ Kp,
         const hf* __restrict__ Vp, hf* __restrict__ Op) {
    extern __shared__ char smc[];
    const uint32_t sb = smem_u32(smc);
    const int tid = threadIdx.x, lane = tid & 31, wid = tid >> 5;
    const int b = blockIdx.z, h = blockIdx.y;
    const int n0 = blockIdx.x * 64;
    const size_t qrow0 = (size_t)b * NN + n0;
    const size_t col0 = (size_t)h * HD;

    {
        const hf* s0 = Qp + qrow0 * DQ + col0;
#pragma unroll
        for (int it = 0; it < 4; it++) {
            int g = it * 128 + tid;
            int r = g >> 3, c = g & 7;
            cp16(sb + r * APB + c * 16, s0 + (size_t)r * DQ + c * 8);
        }
    }
    CP_COMMIT();
    CP_WAIT0();
    __syncthreads();

    uint32_t qv[4][4];
#pragma unroll
    for (int k16 = 0; k16 < 4; k16++) {
        uint32_t ao = (uint32_t)(wid * 16 + (lane & 15)) * APB
                    + (uint32_t)(k16 * 16 + (lane >> 4) * 8) * 2;
        ldmx4(qv[k16][0], qv[k16][1], qv[k16][2], qv[k16][3], sb + ao);
    }
    __syncthreads();

    const hf* ksrc = Kp + ((size_t)b * LL) * DQ + col0;
    const hf* vsrc = Vp + ((size_t)b * LL) * DQ + col0;
    auto load_kv = [&](int blk, int s) {
        uint32_t base = sb + s * KV_STAGE;
        size_t roff = (size_t)blk * 64;
#pragma unroll
        for (int it = 0; it < 8; it++) {
            int g = it * 128 + tid;
            int m = g >> 9;
            int r = (g & 511) >> 3, c = g & 7;
            const hf* src = m == 0 ? ksrc : vsrc;
            cp16(base + m * KV_MAT + r * APB + c * 16,
                 src + (roff + r) * DQ + c * 8);
        }
    };

    // log2-domain softmax-1 stats: implicit zero logit -> m=0, l=1 (2^0)
    float m_[2] = {0.f, 0.f}, l_[2] = {1.f, 1.f};
    float o_[8][4];
#pragma unroll
    for (int d = 0; d < 8; d++)
#pragma unroll
        for (int j = 0; j < 4; j++) o_[d][j] = 0.f;

    load_kv(0, 0);
    CP_COMMIT();

    const int NBLK = LL / 64;
    for (int i = 0; i < NBLK; i++) {
        if (i + 1 < NBLK) { load_kv(i + 1, (i + 1) & 1); CP_COMMIT(); CP_WAIT1(); }
        else CP_WAIT0();
        __syncthreads();

        uint32_t stg = sb + (i & 1) * KV_STAGE;

        float s_[8][4];
#pragma unroll
        for (int nt = 0; nt < 8; nt++)
#pragma unroll
            for (int j = 0; j < 4; j++) s_[nt][j] = 0.f;

#pragma unroll
        for (int k16 = 0; k16 < 4; k16++) {
            uint32_t bcol = (uint32_t)(k16 * 16 + ((lane >> 3) & 1) * 8) * 2;
            uint32_t brow = (uint32_t)(lane & 7);
#pragma unroll
            for (int ntp = 0; ntp < 4; ntp++) {
                int nt0 = 2 * ntp, nt1 = nt0 + 1;
                uint32_t ka0, ka1, kb0, kb1;
                ldmx2(ka0, ka1, stg + (brow + nt0 * 8) * APB + bcol);
                ldmx2(kb0, kb1, stg + (brow + nt1 * 8) * APB + bcol);
                mma16816(s_[nt0], qv[k16], ka0, ka1);
                mma16816(s_[nt1], qv[k16], kb0, kb1);
            }
        }

#pragma unroll
        for (int hh = 0; hh < 2; hh++) {
            float mx = s_[0][hh * 2];
#pragma unroll
            for (int nt = 0; nt < 8; nt++)
                mx = fmaxf(mx, fmaxf(s_[nt][hh * 2], s_[nt][hh * 2 + 1]));
            mx = fmaxf(mx, __shfl_xor_sync(0xffffffffu, mx, 1));
            mx = fmaxf(mx, __shfl_xor_sync(0xffffffffu, mx, 2));
            float mn = fmaxf(m_[hh], mx);
            float corr = exp2f(m_[hh] - mn);
            m_[hh] = mn;
            float sum = 0.f;
#pragma unroll
            for (int nt = 0; nt < 8; nt++) {
                float p0 = exp2f(s_[nt][hh * 2] - mn);
                float p1 = exp2f(s_[nt][hh * 2 + 1] - mn);
                s_[nt][hh * 2] = p0; s_[nt][hh * 2 + 1] = p1;
                sum += p0 + p1;
            }
            sum += __shfl_xor_sync(0xffffffffu, sum, 1);
            sum += __shfl_xor_sync(0xffffffffu, sum, 2);
            l_[hh] = l_[hh] * corr + sum;
#pragma unroll
            for (int d = 0; d < 8; d++) {
                o_[d][hh * 2] *= corr; o_[d][hh * 2 + 1] *= corr;
            }
        }

        uint32_t ph[4][4];
#pragma unroll
        for (int j = 0; j < 4; j++) {
            ph[j][0] = pack2(s_[2 * j][0], s_[2 * j][1]);
            ph[j][1] = pack2(s_[2 * j][2], s_[2 * j][3]);
            ph[j][2] = pack2(s_[2 * j + 1][0], s_[2 * j + 1][1]);
            ph[j][3] = pack2(s_[2 * j + 1][2], s_[2 * j + 1][3]);
        }

        uint32_t vbase = stg + KV_MAT;
#pragma unroll
        for (int j = 0; j < 4; j++) {
            uint32_t vrow = (uint32_t)(j * 16 + (lane & 15)) * APB;
#pragma unroll
            for (int dtp = 0; dtp < 4; dtp++) {
                int dt0 = 2 * dtp, dt1 = dt0 + 1;
                uint32_t va0, va1, vb0, vb1;
                ldmx2t(va0, va1, vbase + vrow + dt0 * 16);
                ldmx2t(vb0, vb1, vbase + vrow + dt1 * 16);
                mma16816(o_[dt0], ph[j], va0, va1);
                mma16816(o_[dt1], ph[j], vb0, vb1);
            }
        }
        __syncthreads();
    }

    float inv0 = 1.f / l_[0], inv1 = 1.f / l_[1];
#pragma unroll
    for (int hh = 0; hh < 2; hh++) {
        float inv = hh == 0 ? inv0 : inv1;
        size_t grow = qrow0 + wid * 16 + (lane >> 2) + hh * 8;
#pragma unroll
        for (int dt = 0; dt < 8; dt++) {
            size_t idx = grow * DQ + col0 + dt * 8 + (lane & 3) * 2;
            *(__half2*)(Op + idx) =
                __halves2half2(__float2half_rn(o_[dt][hh * 2] * inv),
                               __float2half_rn(o_[dt][hh * 2 + 1] * inv));
        }
    }
}

// ---------------------------------------------------------------------------
// kernel_launch
// ---------------------------------------------------------------------------
extern "C" void kernel_launch(void* const* d_in, const int* in_sizes, int n_in,
                              void* d_out, int out_size) {
    const float* x_q   = (const float*)d_in[0];
    const float* x_kv  = (const float*)d_in[1];
    const float* qn_g  = (const float*)d_in[2];
    const float* qn_b  = (const float*)d_in[3];
    const float* kvn_g = (const float*)d_in[4];
    const float* kvn_b = (const float*)d_in[5];
    const float* Wq    = (const float*)d_in[6];
    const float* bq    = (const float*)d_in[7];
    const float* Wk    = (const float*)d_in[8];
    const float* bk    = (const float*)d_in[9];
    const float* Wv    = (const float*)d_in[10];
    const float* bv    = (const float*)d_in[11];
    const float* Wo    = (const float*)d_in[12];
    const float* bo    = (const float*)d_in[13];
    const float* n2_g  = (const float*)d_in[14];
    const float* n2_b  = (const float*)d_in[15];
    const float* W1    = (const float*)d_in[16];
    const float* b1    = (const float*)d_in[17];
    const float* W2    = (const float*)d_in[18];
    const float* b2    = (const float*)d_in[19];
    float* out = (float*)d_out;

    hf* hb = nullptr;
    cudaGetSymbolAddress((void**)&hb, g_hf);

    hf* XQ  = hb + (size_t)O_XQ * EM;
    hf* XKV = hb + (size_t)O_XKV * EM;
    hf* ATT = hb + (size_t)O_ATT * EM;
    hf* X2  = hb + (size_t)O_X2 * EM;
    hf* Hb  = hb + (size_t)O_H * EM;
    hf* WQh = hb + (size_t)O_WQ * EM;
    hf* WKh = hb + (size_t)O_WK * EM;
    hf* WVh = hb + (size_t)O_WV * EM;
    hf* WOh = hb + (size_t)O_WO * EM;
    hf* W1h = hb + (size_t)O_W1 * EM;
    hf* W2h = hb + (size_t)O_W2 * EM;
    hf* Qb  = hb + (size_t)O_Q * EM;
    hf* Kb  = hb + (size_t)O_K * EM;
    hf* Vb  = hb + (size_t)O_V * EM;

    cudaFuncSetAttribute(gemm_mma<1>, cudaFuncAttributeMaxDynamicSharedMemorySize, GEMM_SMEM);
    cudaFuncSetAttribute(gemm_mma<2>, cudaFuncAttributeMaxDynamicSharedMemorySize, GEMM_SMEM);
    cudaFuncSetAttribute(gemm_mma<3>, cudaFuncAttributeMaxDynamicSharedMemorySize, GEMM_SMEM);
    cudaFuncSetAttribute(gemm_qkv, cudaFuncAttributeMaxDynamicSharedMemorySize, GEMM_SMEM);
    cudaFuncSetAttribute(attn_mma, cudaFuncAttributeMaxDynamicSharedMemorySize, ATTN_SMEM);

    // 1: all weight converts (3M float4 -> 12288 blocks)
    convert_all_kernel<<<12288, 256>>>(Wq, Wk, Wv, Wo, W1, W2, hb);

    // 2: both input LNs fused
    ln2x_kernel<<<2 * MROWS, 256>>>(x_q, qn_g, qn_b, XQ,
                                    x_kv, kvn_g, kvn_b, XKV);

    // 3: fused Q+K+V projection (scale*log2e folded into Q)
    gemm_qkv<<<dim3(24, MROWS / 128), 128, GEMM_SMEM>>>(
        XQ, XKV, WQh, WKh, WVh, bq, bk, bv, Qb, Kb, Vb);

    // 4: tensor-core attention (ncu-profiled launch)
    attn_mma<<<dim3(NN / 64, HH, BB), 128, ATTN_SMEM>>>(Qb, Kb, Vb, ATT);

    // 5: out projection + residual with x_q
    gemm_mma<1><<<dim3(DQ / 128, MROWS / 128), 128, GEMM_SMEM>>>(
        ATT, WOh, bo, x_q, out, nullptr, DQ, DQ, 1.0f);

    // 6: LN2
    ln_kernel<<<MROWS, 256>>>(out, n2_g, n2_b, X2);

    // 7: MLP up + GELU -> fp16
    gemm_mma<2><<<dim3(DFF / 128, MROWS / 128), 128, GEMM_SMEM>>>(
        X2, W1h, b1, nullptr, nullptr, Hb, DFF, DQ, 1.0f);

    // 8: MLP down + residual accumulate into d_out
    gemm_mma<3><<<dim3(DQ / 128, MROWS / 128), 128, GEMM_SMEM>>>(
        Hb, W2h, b2, nullptr, out, nullptr, DQ, DFF, 1.0f);
}

// round 15
// speedup vs baseline: 1.0570x; 1.0570x over previous
#include <cuda_runtime.h>
#include <cuda_fp16.h>
#include <math.h>
#include <stdint.h>

#define BB   2
#define NN   2048
#define LL   2048
#define DQ   1024
#define HH   16
#define HD   64
#define MROWS 4096
#define DFF  4096
#define LOG2E 1.4426950408889634f

typedef __half hf;

// ---------------------------------------------------------------------------
// Static scratch (fp16), offsets in EM elements.
// ---------------------------------------------------------------------------
#define EM (1024u*1024u)
__device__ __align__(256) hf g_hf[60u * EM];

#define O_XQ  0
#define O_XKV 4
#define O_ATT 8
#define O_X2  12
#define O_H   16
#define O_WQ  32
#define O_WK  33
#define O_WV  34
#define O_WO  35
#define O_W1  36
#define O_W2  40
#define O_Q   44
#define O_K   48
#define O_V   52

// ---------------------------------------------------------------------------
// helpers
// ---------------------------------------------------------------------------
__device__ __forceinline__ uint32_t smem_u32(const void* p) {
    uint32_t a;
    asm("{ .reg .u64 t; cvta.to.shared.u64 t, %1; cvt.u32.u64 %0, t; }" : "=r"(a) : "l"(p));
    return a;
}
__device__ __forceinline__ void ldmx4(uint32_t& r0, uint32_t& r1, uint32_t& r2,
                                      uint32_t& r3, uint32_t a) {
    asm volatile("ldmatrix.sync.aligned.m8n8.x4.shared.b16 {%0,%1,%2,%3}, [%4];"
                 : "=r"(r0), "=r"(r1), "=r"(r2), "=r"(r3) : "r"(a));
}
__device__ __forceinline__ void ldmx2(uint32_t& r0, uint32_t& r1, uint32_t a) {
    asm volatile("ldmatrix.sync.aligned.m8n8.x2.shared.b16 {%0,%1}, [%2];"
                 : "=r"(r0), "=r"(r1) : "r"(a));
}
__device__ __forceinline__ void ldmx2t(uint32_t& r0, uint32_t& r1, uint32_t a) {
    asm volatile("ldmatrix.sync.aligned.m8n8.x2.trans.shared.b16 {%0,%1}, [%2];"
                 : "=r"(r0), "=r"(r1) : "r"(a));
}
__device__ __forceinline__ void mma16816(float* d, const uint32_t* a,
                                         uint32_t b0, uint32_t b1) {
    asm volatile(
        "mma.sync.aligned.m16n8k16.row.col.f32.f16.f16.f32 "
        "{%0,%1,%2,%3}, {%4,%5,%6,%7}, {%8,%9}, {%0,%1,%2,%3};"
        : "+f"(d[0]), "+f"(d[1]), "+f"(d[2]), "+f"(d[3])
        : "r"(a[0]), "r"(a[1]), "r"(a[2]), "r"(a[3]), "r"(b0), "r"(b1));
}
__device__ __forceinline__ void cp16(uint32_t dst, const void* src) {
    asm volatile("cp.async.cg.shared.global [%0], [%1], 16;" :: "r"(dst), "l"(src));
}
#define CP_COMMIT() asm volatile("cp.async.commit_group;" ::: "memory")
#define CP_WAIT0()  asm volatile("cp.async.wait_group 0;" ::: "memory")
#define CP_WAIT1()  asm volatile("cp.async.wait_group 1;" ::: "memory")

__device__ __forceinline__ float gelu_exact(float x) {
    return 0.5f * x * (1.f + erff(x * 0.7071067811865476f));
}
__device__ __forceinline__ uint32_t pack2(float a, float b) {
    __half2 H = __halves2half2(__float2half_rn(a), __float2half_rn(b));
    return *(uint32_t*)&H;
}

// GEMM smem swizzle: pitch 64B, 16B chunk XORed with (row>>1)&3.
__device__ __forceinline__ uint32_t swz(uint32_t row, uint32_t colbyte) {
    return row * 64 + ((((colbyte >> 4) ^ (row >> 1)) & 3u) << 4);
}

// ---------------------------------------------------------------------------
// Fused LayerNorm (two tensors) -> single fp16
// ---------------------------------------------------------------------------
__global__ void ln2x_kernel(const float* __restrict__ xA,
                            const float* __restrict__ gA,
                            const float* __restrict__ bA,
                            hf* __restrict__ yA,
                            const float* __restrict__ xB,
                            const float* __restrict__ gB,
                            const float* __restrict__ bB,
                            hf* __restrict__ yB) {
    int row = blockIdx.x;
    const float* x; const float* g; const float* b; hf* y;
    if (row < MROWS) { x = xA; g = gA; b = bA; y = yA; }
    else { x = xB; g = gB; b = bB; y = yB; row -= MROWS; }

    const float* xr = x + (size_t)row * DQ;
    float v[4];
    float s = 0.f, s2 = 0.f;
#pragma unroll
    for (int i = 0; i < 4; i++) {
        float t = xr[threadIdx.x + i * 256];
        v[i] = t; s += t; s2 += t * t;
    }
#pragma unroll
    for (int o = 16; o > 0; o >>= 1) {
        s  += __shfl_xor_sync(0xffffffffu, s,  o);
        s2 += __shfl_xor_sync(0xffffffffu, s2, o);
    }
    __shared__ float ws[8], ws2[8];
    int w = threadIdx.x >> 5, lane = threadIdx.x & 31;
    if (lane == 0) { ws[w] = s; ws2[w] = s2; }
    __syncthreads();
    if (w == 0) {
        s  = (lane < 8) ? ws[lane]  : 0.f;
        s2 = (lane < 8) ? ws2[lane] : 0.f;
#pragma unroll
        for (int o = 4; o > 0; o >>= 1) {
            s  += __shfl_xor_sync(0xffffffffu, s,  o);
            s2 += __shfl_xor_sync(0xffffffffu, s2, o);
        }
        if (lane == 0) { ws[0] = s; ws2[0] = s2; }
    }
    __syncthreads();
    float mean = ws[0] * (1.f / DQ);
    float var  = ws2[0] * (1.f / DQ) - mean * mean;
    float rstd = rsqrtf(var + 1e-5f);
    size_t base = (size_t)row * DQ;
#pragma unroll
    for (int i = 0; i < 4; i++) {
        int c = threadIdx.x + i * 256;
        float yv = (v[i] - mean) * rstd * g[c] + b[c];
        y[base + c] = __float2half_rn(yv);
    }
}

// single-tensor LN (for LN2)
__global__ void ln_kernel(const float* __restrict__ x,
                          const float* __restrict__ g,
                          const float* __restrict__ b,
                          hf* __restrict__ y) {
    int row = blockIdx.x;
    const float* xr = x + (size_t)row * DQ;
    float v[4];
    float s = 0.f, s2 = 0.f;
#pragma unroll
    for (int i = 0; i < 4; i++) {
        float t = xr[threadIdx.x + i * 256];
        v[i] = t; s += t; s2 += t * t;
    }
#pragma unroll
    for (int o = 16; o > 0; o >>= 1) {
        s  += __shfl_xor_sync(0xffffffffu, s,  o);
        s2 += __shfl_xor_sync(0xffffffffu, s2, o);
    }
    __shared__ float ws[8], ws2[8];
    int w = threadIdx.x >> 5, lane = threadIdx.x & 31;
    if (lane == 0) { ws[w] = s; ws2[w] = s2; }
    __syncthreads();
    if (w == 0) {
        s  = (lane < 8) ? ws[lane]  : 0.f;
        s2 = (lane < 8) ? ws2[lane] : 0.f;
#pragma unroll
        for (int o = 4; o > 0; o >>= 1) {
            s  += __shfl_xor_sync(0xffffffffu, s,  o);
            s2 += __shfl_xor_sync(0xffffffffu, s2, o);
        }
        if (lane == 0) { ws[0] = s; ws2[0] = s2; }
    }
    __syncthreads();
    float mean = ws[0] * (1.f / DQ);
    float var  = ws2[0] * (1.f / DQ) - mean * mean;
    float rstd = rsqrtf(var + 1e-5f);
    size_t base = (size_t)row * DQ;
#pragma unroll
    for (int i = 0; i < 4; i++) {
        int c = threadIdx.x + i * 256;
        float yv = (v[i] - mean) * rstd * g[c] + b[c];
        y[base + c] = __float2half_rn(yv);
    }
}

// ---------------------------------------------------------------------------
// Single fused weight convert: all 6 weights -> fp16. 3M float4 entries.
// ---------------------------------------------------------------------------
__global__ void convert_all_kernel(
    const float* __restrict__ wq, const float* __restrict__ wk,
    const float* __restrict__ wv, const float* __restrict__ wo,
    const float* __restrict__ w1, const float* __restrict__ w2,
    hf* __restrict__ base) {
    int i = blockIdx.x * blockDim.x + threadIdx.x;   // 0 .. 3M-1
    const float* w; hf* h; int off;
    if (i < (1 << 20)) {
        int seg = i >> 18;
        off = i & 0x3FFFF;
        w = seg == 0 ? wq : seg == 1 ? wk : seg == 2 ? wv : wo;
        h = base + (size_t)(O_WQ + seg) * EM;
    } else {
        int j = i - (1 << 20);
        int seg = j >> 20;
        off = j & 0xFFFFF;
        w = seg == 0 ? w1 : w2;
        h = base + (size_t)(seg == 0 ? O_W1 : O_W2) * EM;
    }
    float4 v = ((const float4*)w)[off];
    __half2* hp = (__half2*)(h + (size_t)off * 4);
    hp[0] = __halves2half2(__float2half_rn(v.x), __float2half_rn(v.y));
    hp[1] = __halves2half2(__float2half_rn(v.z), __float2half_rn(v.w));
}

// ---------------------------------------------------------------------------
// HMMA GEMM core: fp16 operands, fp32 accumulate. 256 threads, 8 warps,
// CTA 128x128, warp tile 64x32 (R13 config), BK=64 per pipeline stage
// (two k32 sub-blocks per sync), 3-stage cp.async, pitch-64 XOR swizzle.
// EPI: 1 bias+res->fp32; 2 gelu->fp16; 3 bias+C rmw; 5 (acc+bias)*alpha->fp16
// ---------------------------------------------------------------------------
#define MAT_BYTES (128 * 64)          // 8192 (one matrix, one k32 sub-block)
#define STAGE_BYTES (4 * MAT_BYTES)   // 32768: A_k0, A_k1, B_k0, B_k1
#define GEMM_SMEM (3 * STAGE_BYTES)   // 98304

template <int EPI>
__device__ __forceinline__ void gemm_core(
    const hf* __restrict__ A, const hf* __restrict__ B,
    const float* __restrict__ bias, const float* __restrict__ res,
    float* __restrict__ C, hf* __restrict__ Ho,
    int N, int K, float alpha, size_t m0, size_t n0, char* smc) {
    const int tid = threadIdx.x, lane = tid & 31, wid = tid >> 5;
    const int wm = wid & 1, wn = wid >> 1;
    const uint32_t sbase = smem_u32(smc);

    const hf* gsrc0 = A + m0 * K;
    const hf* gsrc1 = B + n0 * K;

    // load 64 k-cols: layout [A_k0][A_k1][B_k0][B_k1], each 8KB
    auto load_stage = [&](int s, int kt) {
        uint32_t base = sbase + s * STAGE_BYTES;
#pragma unroll
        for (int i = 0; i < 8; i++) {
            int g = i * 256 + tid;             // 0..2047
            int t = g >> 10;                   // 0 A, 1 B
            int idx = g & 1023;
            int c = idx >> 9;                  // k32 sub-block
            int row = (idx & 511) >> 2, seg = idx & 3;
            const hf* src = (t == 0 ? gsrc0 : gsrc1);
            cp16(base + (t * 2 + c) * MAT_BYTES + swz((uint32_t)row, (uint32_t)(seg * 16)),
                 src + (size_t)row * K + kt + c * 32 + seg * 8);
        }
    };

    float acc[4][4][4];
#pragma unroll
    for (int a = 0; a < 4; a++)
#pragma unroll
        for (int b = 0; b < 4; b++)
#pragma unroll
            for (int c = 0; c < 4; c++) acc[a][b][c] = 0.f;

    const int nk = K >> 6;
    load_stage(0, 0);
    CP_COMMIT();
    load_stage(1, 64);
    CP_COMMIT();

    const uint32_t brow = (uint32_t)(wn * 32 + ((lane >> 4) & 1) * 8 + (lane & 7));
    const uint32_t bcolh = (uint32_t)(((lane >> 3) & 1) * 16);
    const uint32_t arow = (uint32_t)(wm * 64 + (lane & 15));
    const uint32_t acolh = (uint32_t)((lane >> 4) * 16);

    int stage = 0;
    for (int cc = 0; cc < nk; cc++) {
        if (cc + 1 < nk) CP_WAIT1(); else CP_WAIT0();
        __syncthreads();
        if (cc + 2 < nk) {
            int ns = stage + 2; if (ns >= 3) ns -= 3;
            load_stage(ns, (cc + 2) << 6);
            CP_COMMIT();
        }

        uint32_t st = sbase + stage * STAGE_BYTES;
#pragma unroll
        for (int c32 = 0; c32 < 2; c32++) {
            uint32_t sA = st + c32 * MAT_BYTES;
            uint32_t sB = st + (2 + c32) * MAT_BYTES;

            uint32_t Bv[2][8];
#pragma unroll
            for (int k16 = 0; k16 < 2; k16++) {
                uint32_t bcol = (uint32_t)(k16 * 32) + bcolh;
#pragma unroll
                for (int pr = 0; pr < 2; pr++) {
                    uint32_t bo = swz(brow + pr * 16, bcol);
                    ldmx4(Bv[k16][pr * 4 + 0], Bv[k16][pr * 4 + 1],
                          Bv[k16][pr * 4 + 2], Bv[k16][pr * 4 + 3], sB + bo);
                }
            }

#pragma unroll
            for (int mt = 0; mt < 4; mt++) {
#pragma unroll
                for (int k16 = 0; k16 < 2; k16++) {
                    uint32_t ao = swz(arow + mt * 16, (uint32_t)(k16 * 32) + acolh);
                    uint32_t av[4];
                    ldmx4(av[0], av[1], av[2], av[3], sA + ao);
#pragma unroll
                    for (int nt = 0; nt < 4; nt++)
                        mma16816(acc[mt][nt], av, Bv[k16][nt * 2], Bv[k16][nt * 2 + 1]);
                }
            }
        }
        stage++; if (stage >= 3) stage -= 3;
    }

#pragma unroll
    for (int mt = 0; mt < 4; mt++) {
        int r0 = wm * 64 + mt * 16 + (lane >> 2);
#pragma unroll
        for (int nt = 0; nt < 4; nt++) {
            size_t gcol = n0 + wn * 32 + nt * 8 + (lane & 3) * 2;
            float2 bb = *(const float2*)(bias + gcol);
#pragma unroll
            for (int h = 0; h < 2; h++) {
                size_t grow = m0 + r0 + h * 8;
                size_t idx = grow * (size_t)N + gcol;
                float v0 = acc[mt][nt][h * 2 + 0] + bb.x;
                float v1 = acc[mt][nt][h * 2 + 1] + bb.y;
                if (EPI == 1) {
                    float2 rr = *(const float2*)(res + idx);
                    v0 += rr.x; v1 += rr.y;
                }
                if (EPI == 3) {
                    float2 rr = *(const float2*)(C + idx);
                    v0 += rr.x; v1 += rr.y;
                }
                if (EPI == 2) {
                    v0 = gelu_exact(v0); v1 = gelu_exact(v1);
                    *(__half2*)(Ho + idx) =
                        __halves2half2(__float2half_rn(v0), __float2half_rn(v1));
                } else if (EPI == 5) {
                    v0 *= alpha; v1 *= alpha;
                    *(__half2*)(Ho + idx) =
                        __halves2half2(__float2half_rn(v0), __float2half_rn(v1));
                } else {
                    float2 o; o.x = v0; o.y = v1;
                    *(float2*)(C + idx) = o;
                }
            }
        }
    }
}

template <int EPI>
__global__ void __launch_bounds__(256, 2)
gemm_mma(const hf* __restrict__ A, const hf* __restrict__ B,
         const float* __restrict__ bias, const float* __restrict__ res,
         float* __restrict__ C, hf* __restrict__ Ho,
         int N, int K, float alpha) {
    extern __shared__ char smc[];
    gemm_core<EPI>(A, B, bias, res, C, Ho, N, K, alpha,
                   (size_t)blockIdx.y * 128, (size_t)blockIdx.x * 128, smc);
}

// Fused Q/K/V projection
__global__ void __launch_bounds__(256, 2)
gemm_qkv(const hf* __restrict__ XQ, const hf* __restrict__ XKV,
         const hf* __restrict__ WQ, const hf* __restrict__ WK,
         const hf* __restrict__ WV,
         const float* __restrict__ bq, const float* __restrict__ bk,
         const float* __restrict__ bv,
         hf* __restrict__ Q, hf* __restrict__ K, hf* __restrict__ V) {
    extern __shared__ char smc[];
    size_t m0 = (size_t)blockIdx.y * 128;
    int xb = blockIdx.x;
    if (xb < 8) {
        // fold softmax scale AND log2(e) into Q so attention uses exp2
        gemm_core<5>(XQ, WQ, bq, nullptr, nullptr, Q,
                     DQ, DQ, 0.125f * LOG2E, m0, (size_t)xb * 128, smc);
    } else if (xb < 16) {
        gemm_core<5>(XKV, WK, bk, nullptr, nullptr, K,
                     DQ, DQ, 1.0f, m0, (size_t)(xb - 8) * 128, smc);
    } else {
        gemm_core<5>(XKV, WV, bv, nullptr, nullptr, V,
                     DQ, DQ, 1.0f, m0, (size_t)(xb - 16) * 128, smc);
    }
}

// ---------------------------------------------------------------------------
// Tensor-core flash attention, softmax-1 in log2 domain (Q pre-scaled).
// 128 threads x 64 q-rows, 4 CTAs/SM. (R14 version — kept.)
// ---------------------------------------------------------------------------
#define APB 144
#define KV_MAT (64 * APB)            // 9216
#define KV_STAGE (2 * KV_MAT)        // 18432
#define ATTN_SMEM (2 * KV_STAGE)     // 36864

__global__ void __launch_bounds__(128, 4)
attn_mma(const hf* __restrict__ Qp, const hf* __restrict__ Kp,
         const hf* __restrict__ Vp, hf* __restrict__ Op) {
    extern __shared__ char smc[];
    const uint32_t sb = smem_u32(smc);
    const int tid = threadIdx.x, lane = tid & 31, wid = tid >> 5;
    const int b = blockIdx.z, h = blockIdx.y;
    const int n0 = blockIdx.x * 64;
    const size_t qrow0 = (size_t)b * NN + n0;
    const size_t col0 = (size_t)h * HD;

    {
        const hf* s0 = Qp + qrow0 * DQ + col0;
#pragma unroll
        for (int it = 0; it < 4; it++) {
            int g = it * 128 + tid;
            int r = g >> 3, c = g & 7;
            cp16(sb + r * APB + c * 16, s0 + (size_t)r * DQ + c * 8);
        }
    }
    CP_COMMIT();
    CP_WAIT0();
    __syncthreads();

    uint32_t qv[4][4];
#pragma unroll
    for (int k16 = 0; k16 < 4; k16++) {
        uint32_t ao = (uint32_t)(wid * 16 + (lane & 15)) * APB
                    + (uint32_t)(k16 * 16 + (lane >> 4) * 8) * 2;
        ldmx4(qv[k16][0], qv[k16][1], qv[k16][2], qv[k16][3], sb + ao);
    }
    __syncthreads();

    const hf* ksrc = Kp + ((size_t)b * LL) * DQ + col0;
    const hf* vsrc = Vp + ((size_t)b * LL) * DQ + col0;
    auto load_kv = [&](int blk, int s) {
        uint32_t base = sb + s * KV_STAGE;
        size_t roff = (size_t)blk * 64;
#pragma unroll
        for (int it = 0; it < 8; it++) {
            int g = it * 128 + tid;
            int m = g >> 9;
            int r = (g & 511) >> 3, c = g & 7;
            const hf* src = m == 0 ? ksrc : vsrc;
            cp16(base + m * KV_MAT + r * APB + c * 16,
                 src + (roff + r) * DQ + c * 8);
        }
    };

    float m_[2] = {0.f, 0.f}, l_[2] = {1.f, 1.f};
    float o_[8][4];
#pragma unroll
    for (int d = 0; d < 8; d++)
#pragma unroll
        for (int j = 0; j < 4; j++) o_[d][j] = 0.f;

    load_kv(0, 0);
    CP_COMMIT();

    const int NBLK = LL / 64;
    for (int i = 0; i < NBLK; i++) {
        if (i + 1 < NBLK) { load_kv(i + 1, (i + 1) & 1); CP_COMMIT(); CP_WAIT1(); }
        else CP_WAIT0();
        __syncthreads();

        uint32_t stg = sb + (i & 1) * KV_STAGE;

        float s_[8][4];
#pragma unroll
        for (int nt = 0; nt < 8; nt++)
#pragma unroll
            for (int j = 0; j < 4; j++) s_[nt][j] = 0.f;

#pragma unroll
        for (int k16 = 0; k16 < 4; k16++) {
            uint32_t bcol = (uint32_t)(k16 * 16 + ((lane >> 3) & 1) * 8) * 2;
            uint32_t brow = (uint32_t)(lane & 7);
#pragma unroll
            for (int ntp = 0; ntp < 4; ntp++) {
                int nt0 = 2 * ntp, nt1 = nt0 + 1;
                uint32_t ka0, ka1, kb0, kb1;
                ldmx2(ka0, ka1, stg + (brow + nt0 * 8) * APB + bcol);
                ldmx2(kb0, kb1, stg + (brow + nt1 * 8) * APB + bcol);
                mma16816(s_[nt0], qv[k16], ka0, ka1);
                mma16816(s_[nt1], qv[k16], kb0, kb1);
            }
        }

#pragma unroll
        for (int hh = 0; hh < 2; hh++) {
            float mx = s_[0][hh * 2];
#pragma unroll
            for (int nt = 0; nt < 8; nt++)
                mx = fmaxf(mx, fmaxf(s_[nt][hh * 2], s_[nt][hh * 2 + 1]));
            mx = fmaxf(mx, __shfl_xor_sync(0xffffffffu, mx, 1));
            mx = fmaxf(mx, __shfl_xor_sync(0xffffffffu, mx, 2));
            float mn = fmaxf(m_[hh], mx);
            float corr = exp2f(m_[hh] - mn);
            m_[hh] = mn;
            float sum = 0.f;
#pragma unroll
            for (int nt = 0; nt < 8; nt++) {
                float p0 = exp2f(s_[nt][hh * 2] - mn);
                float p1 = exp2f(s_[nt][hh * 2 + 1] - mn);
                s_[nt][hh * 2] = p0; s_[nt][hh * 2 + 1] = p1;
                sum += p0 + p1;
            }
            sum += __shfl_xor_sync(0xffffffffu, sum, 1);
            sum += __shfl_xor_sync(0xffffffffu, sum, 2);
            l_[hh] = l_[hh] * corr + sum;
#pragma unroll
            for (int d = 0; d < 8; d++) {
                o_[d][hh * 2] *= corr; o_[d][hh * 2 + 1] *= corr;
            }
        }

        uint32_t ph[4][4];
#pragma unroll
        for (int j = 0; j < 4; j++) {
            ph[j][0] = pack2(s_[2 * j][0], s_[2 * j][1]);
            ph[j][1] = pack2(s_[2 * j][2], s_[2 * j][3]);
            ph[j][2] = pack2(s_[2 * j + 1][0], s_[2 * j + 1][1]);
            ph[j][3] = pack2(s_[2 * j + 1][2], s_[2 * j + 1][3]);
        }

        uint32_t vbase = stg + KV_MAT;
#pragma unroll
        for (int j = 0; j < 4; j++) {
            uint32_t vrow = (uint32_t)(j * 16 + (lane & 15)) * APB;
#pragma unroll
            for (int dtp = 0; dtp < 4; dtp++) {
                int dt0 = 2 * dtp, dt1 = dt0 + 1;
                uint32_t va0, va1, vb0, vb1;
                ldmx2t(va0, va1, vbase + vrow + dt0 * 16);
                ldmx2t(vb0, vb1, vbase + vrow + dt1 * 16);
                mma16816(o_[dt0], ph[j], va0, va1);
                mma16816(o_[dt1], ph[j], vb0, vb1);
            }
        }
        __syncthreads();
    }

    float inv0 = 1.f / l_[0], inv1 = 1.f / l_[1];
#pragma unroll
    for (int hh = 0; hh < 2; hh++) {
        float inv = hh == 0 ? inv0 : inv1;
        size_t grow = qrow0 + wid * 16 + (lane >> 2) + hh * 8;
#pragma unroll
        for (int dt = 0; dt < 8; dt++) {
            size_t idx = grow * DQ + col0 + dt * 8 + (lane & 3) * 2;
            *(__half2*)(Op + idx) =
                __halves2half2(__float2half_rn(o_[dt][hh * 2] * inv),
                               __float2half_rn(o_[dt][hh * 2 + 1] * inv));
        }
    }
}

// ---------------------------------------------------------------------------
// kernel_launch
// ---------------------------------------------------------------------------
extern "C" void kernel_launch(void* const* d_in, const int* in_sizes, int n_in,
                              void* d_out, int out_size) {
    const float* x_q   = (const float*)d_in[0];
    const float* x_kv  = (const float*)d_in[1];
    const float* qn_g  = (const float*)d_in[2];
    const float* qn_b  = (const float*)d_in[3];
    const float* kvn_g = (const float*)d_in[4];
    const float* kvn_b = (const float*)d_in[5];
    const float* Wq    = (const float*)d_in[6];
    const float* bq    = (const float*)d_in[7];
    const float* Wk    = (const float*)d_in[8];
    const float* bk    = (const float*)d_in[9];
    const float* Wv    = (const float*)d_in[10];
    const float* bv    = (const float*)d_in[11];
    const float* Wo    = (const float*)d_in[12];
    const float* bo    = (const float*)d_in[13];
    const float* n2_g  = (const float*)d_in[14];
    const float* n2_b  = (const float*)d_in[15];
    const float* W1    = (const float*)d_in[16];
    const float* b1    = (const float*)d_in[17];
    const float* W2    = (const float*)d_in[18];
    const float* b2    = (const float*)d_in[19];
    float* out = (float*)d_out;

    hf* hb = nullptr;
    cudaGetSymbolAddress((void**)&hb, g_hf);

    hf* XQ  = hb + (size_t)O_XQ * EM;
    hf* XKV = hb + (size_t)O_XKV * EM;
    hf* ATT = hb + (size_t)O_ATT * EM;
    hf* X2  = hb + (size_t)O_X2 * EM;
    hf* Hb  = hb + (size_t)O_H * EM;
    hf* WQh = hb + (size_t)O_WQ * EM;
    hf* WKh = hb + (size_t)O_WK * EM;
    hf* WVh = hb + (size_t)O_WV * EM;
    hf* WOh = hb + (size_t)O_WO * EM;
    hf* W1h = hb + (size_t)O_W1 * EM;
    hf* W2h = hb + (size_t)O_W2 * EM;
    hf* Qb  = hb + (size_t)O_Q * EM;
    hf* Kb  = hb + (size_t)O_K * EM;
    hf* Vb  = hb + (size_t)O_V * EM;

    cudaFuncSetAttribute(gemm_mma<1>, cudaFuncAttributeMaxDynamicSharedMemorySize, GEMM_SMEM);
    cudaFuncSetAttribute(gemm_mma<2>, cudaFuncAttributeMaxDynamicSharedMemorySize, GEMM_SMEM);
    cudaFuncSetAttribute(gemm_mma<3>, cudaFuncAttributeMaxDynamicSharedMemorySize, GEMM_SMEM);
    cudaFuncSetAttribute(gemm_qkv, cudaFuncAttributeMaxDynamicSharedMemorySize, GEMM_SMEM);
    cudaFuncSetAttribute(attn_mma, cudaFuncAttributeMaxDynamicSharedMemorySize, ATTN_SMEM);

    // 1: all weight converts (3M float4 -> 12288 blocks)
    convert_all_kernel<<<12288, 256>>>(Wq, Wk, Wv, Wo, W1, W2, hb);

    // 2: both input LNs fused
    ln2x_kernel<<<2 * MROWS, 256>>>(x_q, qn_g, qn_b, XQ,
                                    x_kv, kvn_g, kvn_b, XKV);

    // 3: fused Q+K+V projection (scale*log2e folded into Q)
    gemm_qkv<<<dim3(24, MROWS / 128), 256, GEMM_SMEM>>>(
        XQ, XKV, WQh, WKh, WVh, bq, bk, bv, Qb, Kb, Vb);

    // 4: tensor-core attention (ncu-profiled launch)
    attn_mma<<<dim3(NN / 64, HH, BB), 128, ATTN_SMEM>>>(Qb, Kb, Vb, ATT);

    // 5: out projection + residual with x_q
    gemm_mma<1><<<dim3(DQ / 128, MROWS / 128), 256, GEMM_SMEM>>>(
        ATT, WOh, bo, x_q, out, nullptr, DQ, DQ, 1.0f);

    // 6: LN2
    ln_kernel<<<MROWS, 256>>>(out, n2_g, n2_b, X2);

    // 7: MLP up + GELU -> fp16
    gemm_mma<2><<<dim3(DFF / 128, MROWS / 128), 256, GEMM_SMEM>>>(
        X2, W1h, b1, nullptr, nullptr, Hb, DFF, DQ, 1.0f);

    // 8: MLP down + residual accumulate into d_out
    gemm_mma<3><<<dim3(DQ / 128, MROWS / 128), 256, GEMM_SMEM>>>(
        Hb, W2h, b2, nullptr, out, nullptr, DQ, DFF, 1.0f);
}

// round 16
// speedup vs baseline: 1.0758x; 1.0178x over previous
#include <cuda_runtime.h>
#include <cuda_fp16.h>
#include <math.h>
#include <stdint.h>

#define BB   2
#define NN   2048
#define LL   2048
#define DQ   1024
#define HH   16
#define HD   64
#define MROWS 4096
#define DFF  4096
#define LOG2E 1.4426950408889634f

typedef __half hf;

// ---------------------------------------------------------------------------
// Static scratch (fp16), offsets in EM elements.
// ---------------------------------------------------------------------------
#define EM (1024u*1024u)
__device__ __align__(256) hf g_hf[60u * EM];

#define O_XQ  0
#define O_XKV 4
#define O_ATT 8
#define O_X2  12
#define O_H   16
#define O_WQ  32
#define O_WK  33
#define O_WV  34
#define O_WO  35
#define O_W1  36
#define O_W2  40
#define O_Q   44
#define O_K   48
#define O_V   52

// ---------------------------------------------------------------------------
// helpers
// ---------------------------------------------------------------------------
__device__ __forceinline__ uint32_t smem_u32(const void* p) {
    uint32_t a;
    asm("{ .reg .u64 t; cvta.to.shared.u64 t, %1; cvt.u32.u64 %0, t; }" : "=r"(a) : "l"(p));
    return a;
}
__device__ __forceinline__ void ldmx4(uint32_t& r0, uint32_t& r1, uint32_t& r2,
                                      uint32_t& r3, uint32_t a) {
    asm volatile("ldmatrix.sync.aligned.m8n8.x4.shared.b16 {%0,%1,%2,%3}, [%4];"
                 : "=r"(r0), "=r"(r1), "=r"(r2), "=r"(r3) : "r"(a));
}
__device__ __forceinline__ void ldmx2(uint32_t& r0, uint32_t& r1, uint32_t a) {
    asm volatile("ldmatrix.sync.aligned.m8n8.x2.shared.b16 {%0,%1}, [%2];"
                 : "=r"(r0), "=r"(r1) : "r"(a));
}
__device__ __forceinline__ void ldmx2t(uint32_t& r0, uint32_t& r1, uint32_t a) {
    asm volatile("ldmatrix.sync.aligned.m8n8.x2.trans.shared.b16 {%0,%1}, [%2];"
                 : "=r"(r0), "=r"(r1) : "r"(a));
}
__device__ __forceinline__ void mma16816(float* d, const uint32_t* a,
                                         uint32_t b0, uint32_t b1) {
    asm volatile(
        "mma.sync.aligned.m16n8k16.row.col.f32.f16.f16.f32 "
        "{%0,%1,%2,%3}, {%4,%5,%6,%7}, {%8,%9}, {%0,%1,%2,%3};"
        : "+f"(d[0]), "+f"(d[1]), "+f"(d[2]), "+f"(d[3])
        : "r"(a[0]), "r"(a[1]), "r"(a[2]), "r"(a[3]), "r"(b0), "r"(b1));
}
__device__ __forceinline__ void cp16(uint32_t dst, const void* src) {
    asm volatile("cp.async.cg.shared.global [%0], [%1], 16;" :: "r"(dst), "l"(src));
}
#define CP_COMMIT() asm volatile("cp.async.commit_group;" ::: "memory")
#define CP_WAIT0()  asm volatile("cp.async.wait_group 0;" ::: "memory")
#define CP_WAIT1()  asm volatile("cp.async.wait_group 1;" ::: "memory")

__device__ __forceinline__ float gelu_exact(float x) {
    return 0.5f * x * (1.f + erff(x * 0.7071067811865476f));
}
__device__ __forceinline__ uint32_t pack2(float a, float b) {
    __half2 H = __halves2half2(__float2half_rn(a), __float2half_rn(b));
    return *(uint32_t*)&H;
}

// GEMM smem swizzle: pitch 64B, 16B chunk XORed with (row>>1)&3.
__device__ __forceinline__ uint32_t swz(uint32_t row, uint32_t colbyte) {
    return row * 64 + ((((colbyte >> 4) ^ (row >> 1)) & 3u) << 4);
}

// ---------------------------------------------------------------------------
// Fused LayerNorm (two tensors) -> single fp16
// ---------------------------------------------------------------------------
__global__ void ln2x_kernel(const float* __restrict__ xA,
                            const float* __restrict__ gA,
                            const float* __restrict__ bA,
                            hf* __restrict__ yA,
                            const float* __restrict__ xB,
                            const float* __restrict__ gB,
                            const float* __restrict__ bB,
                            hf* __restrict__ yB) {
    int row = blockIdx.x;
    const float* x; const float* g; const float* b; hf* y;
    if (row < MROWS) { x = xA; g = gA; b = bA; y = yA; }
    else { x = xB; g = gB; b = bB; y = yB; row -= MROWS; }

    const float* xr = x + (size_t)row * DQ;
    float v[4];
    float s = 0.f, s2 = 0.f;
#pragma unroll
    for (int i = 0; i < 4; i++) {
        float t = xr[threadIdx.x + i * 256];
        v[i] = t; s += t; s2 += t * t;
    }
#pragma unroll
    for (int o = 16; o > 0; o >>= 1) {
        s  += __shfl_xor_sync(0xffffffffu, s,  o);
        s2 += __shfl_xor_sync(0xffffffffu, s2, o);
    }
    __shared__ float ws[8], ws2[8];
    int w = threadIdx.x >> 5, lane = threadIdx.x & 31;
    if (lane == 0) { ws[w] = s; ws2[w] = s2; }
    __syncthreads();
    if (w == 0) {
        s  = (lane < 8) ? ws[lane]  : 0.f;
        s2 = (lane < 8) ? ws2[lane] : 0.f;
#pragma unroll
        for (int o = 4; o > 0; o >>= 1) {
            s  += __shfl_xor_sync(0xffffffffu, s,  o);
            s2 += __shfl_xor_sync(0xffffffffu, s2, o);
        }
        if (lane == 0) { ws[0] = s; ws2[0] = s2; }
    }
    __syncthreads();
    float mean = ws[0] * (1.f / DQ);
    float var  = ws2[0] * (1.f / DQ) - mean * mean;
    float rstd = rsqrtf(var + 1e-5f);
    size_t base = (size_t)row * DQ;
#pragma unroll
    for (int i = 0; i < 4; i++) {
        int c = threadIdx.x + i * 256;
        float yv = (v[i] - mean) * rstd * g[c] + b[c];
        y[base + c] = __float2half_rn(yv);
    }
}

// single-tensor LN (for LN2)
__global__ void ln_kernel(const float* __restrict__ x,
                          const float* __restrict__ g,
                          const float* __restrict__ b,
                          hf* __restrict__ y) {
    int row = blockIdx.x;
    const float* xr = x + (size_t)row * DQ;
    float v[4];
    float s = 0.f, s2 = 0.f;
#pragma unroll
    for (int i = 0; i < 4; i++) {
        float t = xr[threadIdx.x + i * 256];
        v[i] = t; s += t; s2 += t * t;
    }
#pragma unroll
    for (int o = 16; o > 0; o >>= 1) {
        s  += __shfl_xor_sync(0xffffffffu, s,  o);
        s2 += __shfl_xor_sync(0xffffffffu, s2, o);
    }
    __shared__ float ws[8], ws2[8];
    int w = threadIdx.x >> 5, lane = threadIdx.x & 31;
    if (lane == 0) { ws[w] = s; ws2[w] = s2; }
    __syncthreads();
    if (w == 0) {
        s  = (lane < 8) ? ws[lane]  : 0.f;
        s2 = (lane < 8) ? ws2[lane] : 0.f;
#pragma unroll
        for (int o = 4; o > 0; o >>= 1) {
            s  += __shfl_xor_sync(0xffffffffu, s,  o);
            s2 += __shfl_xor_sync(0xffffffffu, s2, o);
        }
        if (lane == 0) { ws[0] = s; ws2[0] = s2; }
    }
    __syncthreads();
    float mean = ws[0] * (1.f / DQ);
    float var  = ws2[0] * (1.f / DQ) - mean * mean;
    float rstd = rsqrtf(var + 1e-5f);
    size_t base = (size_t)row * DQ;
#pragma unroll
    for (int i = 0; i < 4; i++) {
        int c = threadIdx.x + i * 256;
        float yv = (v[i] - mean) * rstd * g[c] + b[c];
        y[base + c] = __float2half_rn(yv);
    }
}

// ---------------------------------------------------------------------------
// Single fused weight convert: all 6 weights -> fp16. 3M float4 entries.
// ---------------------------------------------------------------------------
__global__ void convert_all_kernel(
    const float* __restrict__ wq, const float* __restrict__ wk,
    const float* __restrict__ wv, const float* __restrict__ wo,
    const float* __restrict__ w1, const float* __restrict__ w2,
    hf* __restrict__ base) {
    int i = blockIdx.x * blockDim.x + threadIdx.x;   // 0 .. 3M-1
    const float* w; hf* h; int off;
    if (i < (1 << 20)) {
        int seg = i >> 18;
        off = i & 0x3FFFF;
        w = seg == 0 ? wq : seg == 1 ? wk : seg == 2 ? wv : wo;
        h = base + (size_t)(O_WQ + seg) * EM;
    } else {
        int j = i - (1 << 20);
        int seg = j >> 20;
        off = j & 0xFFFFF;
        w = seg == 0 ? w1 : w2;
        h = base + (size_t)(seg == 0 ? O_W1 : O_W2) * EM;
    }
    float4 v = ((const float4*)w)[off];
    __half2* hp = (__half2*)(h + (size_t)off * 4);
    hp[0] = __halves2half2(__float2half_rn(v.x), __float2half_rn(v.y));
    hp[1] = __halves2half2(__float2half_rn(v.z), __float2half_rn(v.w));
}

// ---------------------------------------------------------------------------
// HMMA GEMM core (R13 config): fp16 operands, fp32 accumulate. 256 threads,
// 8 warps, CTA 128x128, warp tile 64x32, BK=32, 3-stage cp.async,
// pitch-64 XOR swizzle, software-pipelined A-fragment prefetch.
// EPI: 1 bias+res->fp32; 2 gelu->fp16; 3 bias+C rmw; 5 (acc+bias)*alpha->fp16
// ---------------------------------------------------------------------------
#define MAT_BYTES (128 * 64)
#define STAGE_BYTES (2 * MAT_BYTES)   // 16384
#define GEMM_SMEM (3 * STAGE_BYTES)   // 49152

template <int EPI>
__device__ __forceinline__ void gemm_core(
    const hf* __restrict__ A, const hf* __restrict__ B,
    const float* __restrict__ bias, const float* __restrict__ res,
    float* __restrict__ C, hf* __restrict__ Ho,
    int N, int K, float alpha, size_t m0, size_t n0, char* smc) {
    const int tid = threadIdx.x, lane = tid & 31, wid = tid >> 5;
    const int wm = wid & 1, wn = wid >> 1;
    const uint32_t sbase = smem_u32(smc);

    const hf* gsrc0 = A + m0 * K;
    const hf* gsrc1 = B + n0 * K;

    auto load_stage = [&](int s, int kt) {
        uint32_t base = sbase + s * STAGE_BYTES;
#pragma unroll
        for (int i = 0; i < 4; i++) {
            const int t = i >> 1;
            int idx = tid + (i & 1) * 256;
            int row = idx >> 2, seg = idx & 3;
            const hf* src = (t == 0 ? gsrc0 : gsrc1);
            cp16(base + t * MAT_BYTES + swz((uint32_t)row, (uint32_t)(seg * 16)),
                 src + (size_t)row * K + kt + seg * 8);
        }
    };

    float acc[4][4][4];
#pragma unroll
    for (int a = 0; a < 4; a++)
#pragma unroll
        for (int b = 0; b < 4; b++)
#pragma unroll
            for (int c = 0; c < 4; c++) acc[a][b][c] = 0.f;

    const int nk = K >> 5;
    load_stage(0, 0);
    CP_COMMIT();
    load_stage(1, 32);
    CP_COMMIT();

    const uint32_t brow = (uint32_t)(wn * 32 + ((lane >> 4) & 1) * 8 + (lane & 7));
    const uint32_t bcolh = (uint32_t)(((lane >> 3) & 1) * 16);
    const uint32_t arow = (uint32_t)(wm * 64 + (lane & 15));
    const uint32_t acolh = (uint32_t)((lane >> 4) * 16);

    int stage = 0;
    for (int cc = 0; cc < nk; cc++) {
        if (cc + 1 < nk) CP_WAIT1(); else CP_WAIT0();
        __syncthreads();
        if (cc + 2 < nk) {
            int ns = stage + 2; if (ns >= 3) ns -= 3;
            load_stage(ns, (cc + 2) << 5);
            CP_COMMIT();
        }

        uint32_t st = sbase + stage * STAGE_BYTES;
        uint32_t sA = st, sB = st + MAT_BYTES;

        uint32_t Bv[2][8];
#pragma unroll
        for (int k16 = 0; k16 < 2; k16++) {
            uint32_t bcol = (uint32_t)(k16 * 32) + bcolh;
#pragma unroll
            for (int pr = 0; pr < 2; pr++) {
                uint32_t bo = swz(brow + pr * 16, bcol);
                ldmx4(Bv[k16][pr * 4 + 0], Bv[k16][pr * 4 + 1],
                      Bv[k16][pr * 4 + 2], Bv[k16][pr * 4 + 3], sB + bo);
            }
        }

        // software-pipelined A fragments: (mt,k16) steps j = mt*2 + k16
        uint32_t av[2][4];
        ldmx4(av[0][0], av[0][1], av[0][2], av[0][3],
              sA + swz(arow, acolh));                       // j=0 (mt0,k0)
#pragma unroll
        for (int j = 0; j < 8; j++) {
            int buf = j & 1;
            if (j + 1 < 8) {
                int mtn = (j + 1) >> 1, k16n = (j + 1) & 1;
                uint32_t ao = swz(arow + mtn * 16, (uint32_t)(k16n * 32) + acolh);
                ldmx4(av[buf ^ 1][0], av[buf ^ 1][1],
                      av[buf ^ 1][2], av[buf ^ 1][3], sA + ao);
            }
            int mt = j >> 1, k16 = j & 1;
#pragma unroll
            for (int nt = 0; nt < 4; nt++)
                mma16816(acc[mt][nt], av[buf], Bv[k16][nt * 2], Bv[k16][nt * 2 + 1]);
        }
        stage++; if (stage >= 3) stage -= 3;
    }

#pragma unroll
    for (int mt = 0; mt < 4; mt++) {
        int r0 = wm * 64 + mt * 16 + (lane >> 2);
#pragma unroll
        for (int nt = 0; nt < 4; nt++) {
            size_t gcol = n0 + wn * 32 + nt * 8 + (lane & 3) * 2;
            float2 bb = *(const float2*)(bias + gcol);
#pragma unroll
            for (int h = 0; h < 2; h++) {
                size_t grow = m0 + r0 + h * 8;
                size_t idx = grow * (size_t)N + gcol;
                float v0 = acc[mt][nt][h * 2 + 0] + bb.x;
                float v1 = acc[mt][nt][h * 2 + 1] + bb.y;
                if (EPI == 1) {
                    float2 rr = *(const float2*)(res + idx);
                    v0 += rr.x; v1 += rr.y;
                }
                if (EPI == 3) {
                    float2 rr = *(const float2*)(C + idx);
                    v0 += rr.x; v1 += rr.y;
                }
                if (EPI == 2) {
                    v0 = gelu_exact(v0); v1 = gelu_exact(v1);
                    *(__half2*)(Ho + idx) =
                        __halves2half2(__float2half_rn(v0), __float2half_rn(v1));
                } else if (EPI == 5) {
                    v0 *= alpha; v1 *= alpha;
                    *(__half2*)(Ho + idx) =
                        __halves2half2(__float2half_rn(v0), __float2half_rn(v1));
                } else {
                    float2 o; o.x = v0; o.y = v1;
                    *(float2*)(C + idx) = o;
                }
            }
        }
    }
}

template <int EPI>
__global__ void __launch_bounds__(256, 2)
gemm_mma(const hf* __restrict__ A, const hf* __restrict__ B,
         const float* __restrict__ bias, const float* __restrict__ res,
         float* __restrict__ C, hf* __restrict__ Ho,
         int N, int K, float alpha) {
    extern __shared__ char smc[];
    gemm_core<EPI>(A, B, bias, res, C, Ho, N, K, alpha,
                   (size_t)blockIdx.y * 128, (size_t)blockIdx.x * 128, smc);
}

// Fused Q/K/V projection
__global__ void __launch_bounds__(256, 2)
gemm_qkv(const hf* __restrict__ XQ, const hf* __restrict__ XKV,
         const hf* __restrict__ WQ, const hf* __restrict__ WK,
         const hf* __restrict__ WV,
         const float* __restrict__ bq, const float* __restrict__ bk,
         const float* __restrict__ bv,
         hf* __restrict__ Q, hf* __restrict__ K, hf* __restrict__ V) {
    extern __shared__ char smc[];
    size_t m0 = (size_t)blockIdx.y * 128;
    int xb = blockIdx.x;
    if (xb < 8) {
        // fold softmax scale AND log2(e) into Q so attention uses exp2
        gemm_core<5>(XQ, WQ, bq, nullptr, nullptr, Q,
                     DQ, DQ, 0.125f * LOG2E, m0, (size_t)xb * 128, smc);
    } else if (xb < 16) {
        gemm_core<5>(XKV, WK, bk, nullptr, nullptr, K,
                     DQ, DQ, 1.0f, m0, (size_t)(xb - 8) * 128, smc);
    } else {
        gemm_core<5>(XKV, WV, bv, nullptr, nullptr, V,
                     DQ, DQ, 1.0f, m0, (size_t)(xb - 16) * 128, smc);
    }
}

// ---------------------------------------------------------------------------
// Tensor-core flash attention, softmax-1 in log2 domain (Q pre-scaled).
// 128 threads x 64 q-rows, 4 CTAs/SM. (R14/R15 version — kept.)
// ---------------------------------------------------------------------------
#define APB 144
#define KV_MAT (64 * APB)            // 9216
#define KV_STAGE (2 * KV_MAT)        // 18432
#define ATTN_SMEM (2 * KV_STAGE)     // 36864

__global__ void __launch_bounds__(128, 4)
attn_mma(const hf* __restrict__ Qp, const hf* __restrict__ Kp,
         const hf* __restrict__ Vp, hf* __restrict__ Op) {
    extern __shared__ char smc[];
    const uint32_t sb = smem_u32(smc);
    const int tid = threadIdx.x, lane = tid & 31, wid = tid >> 5;
    const int b = blockIdx.z, h = blockIdx.y;
    const int n0 = blockIdx.x * 64;
    const size_t qrow0 = (size_t)b * NN + n0;
    const size_t col0 = (size_t)h * HD;

    {
        const hf* s0 = Qp + qrow0 * DQ + col0;
#pragma unroll
        for (int it = 0; it < 4; it++) {
            int g = it * 128 + tid;
            int r = g >> 3, c = g & 7;
            cp16(sb + r * APB + c * 16, s0 + (size_t)r * DQ + c * 8);
        }
    }
    CP_COMMIT();
    CP_WAIT0();
    __syncthreads();

    uint32_t qv[4][4];
#pragma unroll
    for (int k16 = 0; k16 < 4; k16++) {
        uint32_t ao = (uint32_t)(wid * 16 + (lane & 15)) * APB
                    + (uint32_t)(k16 * 16 + (lane >> 4) * 8) * 2;
        ldmx4(qv[k16][0], qv[k16][1], qv[k16][2], qv[k16][3], sb + ao);
    }
    __syncthreads();

    const hf* ksrc = Kp + ((size_t)b * LL) * DQ + col0;
    const hf* vsrc = Vp + ((size_t)b * LL) * DQ + col0;
    auto load_kv = [&](int blk, int s) {
        uint32_t base = sb + s * KV_STAGE;
        size_t roff = (size_t)blk * 64;
#pragma unroll
        for (int it = 0; it < 8; it++) {
            int g = it * 128 + tid;
            int m = g >> 9;
            int r = (g & 511) >> 3, c = g & 7;
            const hf* src = m == 0 ? ksrc : vsrc;
            cp16(base + m * KV_MAT + r * APB + c * 16,
                 src + (roff + r) * DQ + c * 8);
        }
    };

    float m_[2] = {0.f, 0.f}, l_[2] = {1.f, 1.f};
    float o_[8][4];
#pragma unroll
    for (int d = 0; d < 8; d++)
#pragma unroll
        for (int j = 0; j < 4; j++) o_[d][j] = 0.f;

    load_kv(0, 0);
    CP_COMMIT();

    const int NBLK = LL / 64;
    for (int i = 0; i < NBLK; i++) {
        if (i + 1 < NBLK) { load_kv(i + 1, (i + 1) & 1); CP_COMMIT(); CP_WAIT1(); }
        else CP_WAIT0();
        __syncthreads();

        uint32_t stg = sb + (i & 1) * KV_STAGE;

        float s_[8][4];
#pragma unroll
        for (int nt = 0; nt < 8; nt++)
#pragma unroll
            for (int j = 0; j < 4; j++) s_[nt][j] = 0.f;

#pragma unroll
        for (int k16 = 0; k16 < 4; k16++) {
            uint32_t bcol = (uint32_t)(k16 * 16 + ((lane >> 3) & 1) * 8) * 2;
            uint32_t brow = (uint32_t)(lane & 7);
#pragma unroll
            for (int ntp = 0; ntp < 4; ntp++) {
                int nt0 = 2 * ntp, nt1 = nt0 + 1;
                uint32_t ka0, ka1, kb0, kb1;
                ldmx2(ka0, ka1, stg + (brow + nt0 * 8) * APB + bcol);
                ldmx2(kb0, kb1, stg + (brow + nt1 * 8) * APB + bcol);
                mma16816(s_[nt0], qv[k16], ka0, ka1);
                mma16816(s_[nt1], qv[k16], kb0, kb1);
            }
        }

#pragma unroll
        for (int hh = 0; hh < 2; hh++) {
            float mx = s_[0][hh * 2];
#pragma unroll
            for (int nt = 0; nt < 8; nt++)
                mx = fmaxf(mx, fmaxf(s_[nt][hh * 2], s_[nt][hh * 2 + 1]));
            mx = fmaxf(mx, __shfl_xor_sync(0xffffffffu, mx, 1));
            mx = fmaxf(mx, __shfl_xor_sync(0xffffffffu, mx, 2));
            float mn = fmaxf(m_[hh], mx);
            float corr = exp2f(m_[hh] - mn);
            m_[hh] = mn;
            float sum = 0.f;
#pragma unroll
            for (int nt = 0; nt < 8; nt++) {
                float p0 = exp2f(s_[nt][hh * 2] - mn);
                float p1 = exp2f(s_[nt][hh * 2 + 1] - mn);
                s_[nt][hh * 2] = p0; s_[nt][hh * 2 + 1] = p1;
                sum += p0 + p1;
            }
            sum += __shfl_xor_sync(0xffffffffu, sum, 1);
            sum += __shfl_xor_sync(0xffffffffu, sum, 2);
            l_[hh] = l_[hh] * corr + sum;
#pragma unroll
            for (int d = 0; d < 8; d++) {
                o_[d][hh * 2] *= corr; o_[d][hh * 2 + 1] *= corr;
            }
        }

        uint32_t ph[4][4];
#pragma unroll
        for (int j = 0; j < 4; j++) {
            ph[j][0] = pack2(s_[2 * j][0], s_[2 * j][1]);
            ph[j][1] = pack2(s_[2 * j][2], s_[2 * j][3]);
            ph[j][2] = pack2(s_[2 * j + 1][0], s_[2 * j + 1][1]);
            ph[j][3] = pack2(s_[2 * j + 1][2], s_[2 * j + 1][3]);
        }

        uint32_t vbase = stg + KV_MAT;
#pragma unroll
        for (int j = 0; j < 4; j++) {
            uint32_t vrow = (uint32_t)(j * 16 + (lane & 15)) * APB;
#pragma unroll
            for (int dtp = 0; dtp < 4; dtp++) {
                int dt0 = 2 * dtp, dt1 = dt0 + 1;
                uint32_t va0, va1, vb0, vb1;
                ldmx2t(va0, va1, vbase + vrow + dt0 * 16);
                ldmx2t(vb0, vb1, vbase + vrow + dt1 * 16);
                mma16816(o_[dt0], ph[j], va0, va1);
                mma16816(o_[dt1], ph[j], vb0, vb1);
            }
        }
        __syncthreads();
    }

    float inv0 = 1.f / l_[0], inv1 = 1.f / l_[1];
#pragma unroll
    for (int hh = 0; hh < 2; hh++) {
        float inv = hh == 0 ? inv0 : inv1;
        size_t grow = qrow0 + wid * 16 + (lane >> 2) + hh * 8;
#pragma unroll
        for (int dt = 0; dt < 8; dt++) {
            size_t idx = grow * DQ + col0 + dt * 8 + (lane & 3) * 2;
            *(__half2*)(Op + idx) =
                __halves2half2(__float2half_rn(o_[dt][hh * 2] * inv),
                               __float2half_rn(o_[dt][hh * 2 + 1] * inv));
        }
    }
}

// ---------------------------------------------------------------------------
// kernel_launch
// ---------------------------------------------------------------------------
extern "C" void kernel_launch(void* const* d_in, const int* in_sizes, int n_in,
                              void* d_out, int out_size) {
    const float* x_q   = (const float*)d_in[0];
    const float* x_kv  = (const float*)d_in[1];
    const float* qn_g  = (const float*)d_in[2];
    const float* qn_b  = (const float*)d_in[3];
    const float* kvn_g = (const float*)d_in[4];
    const float* kvn_b = (const float*)d_in[5];
    const float* Wq    = (const float*)d_in[6];
    const float* bq    = (const float*)d_in[7];
    const float* Wk    = (const float*)d_in[8];
    const float* bk    = (const float*)d_in[9];
    const float* Wv    = (const float*)d_in[10];
    const float* bv    = (const float*)d_in[11];
    const float* Wo    = (const float*)d_in[12];
    const float* bo    = (const float*)d_in[13];
    const float* n2_g  = (const float*)d_in[14];
    const float* n2_b  = (const float*)d_in[15];
    const float* W1    = (const float*)d_in[16];
    const float* b1    = (const float*)d_in[17];
    const float* W2    = (const float*)d_in[18];
    const float* b2    = (const float*)d_in[19];
    float* out = (float*)d_out;

    hf* hb = nullptr;
    cudaGetSymbolAddress((void**)&hb, g_hf);

    hf* XQ  = hb + (size_t)O_XQ * EM;
    hf* XKV = hb + (size_t)O_XKV * EM;
    hf* ATT = hb + (size_t)O_ATT * EM;
    hf* X2  = hb + (size_t)O_X2 * EM;
    hf* Hb  = hb + (size_t)O_H * EM;
    hf* WQh = hb + (size_t)O_WQ * EM;
    hf* WKh = hb + (size_t)O_WK * EM;
    hf* WVh = hb + (size_t)O_WV * EM;
    hf* WOh = hb + (size_t)O_WO * EM;
    hf* W1h = hb + (size_t)O_W1 * EM;
    hf* W2h = hb + (size_t)O_W2 * EM;
    hf* Qb  = hb + (size_t)O_Q * EM;
    hf* Kb  = hb + (size_t)O_K * EM;
    hf* Vb  = hb + (size_t)O_V * EM;

    cudaFuncSetAttribute(gemm_mma<1>, cudaFuncAttributeMaxDynamicSharedMemorySize, GEMM_SMEM);
    cudaFuncSetAttribute(gemm_mma<2>, cudaFuncAttributeMaxDynamicSharedMemorySize, GEMM_SMEM);
    cudaFuncSetAttribute(gemm_mma<3>, cudaFuncAttributeMaxDynamicSharedMemorySize, GEMM_SMEM);
    cudaFuncSetAttribute(gemm_qkv, cudaFuncAttributeMaxDynamicSharedMemorySize, GEMM_SMEM);
    cudaFuncSetAttribute(attn_mma, cudaFuncAttributeMaxDynamicSharedMemorySize, ATTN_SMEM);

    // 1: all weight converts (3M float4 -> 12288 blocks)
    convert_all_kernel<<<12288, 256>>>(Wq, Wk, Wv, Wo, W1, W2, hb);

    // 2: both input LNs fused
    ln2x_kernel<<<2 * MROWS, 256>>>(x_q, qn_g, qn_b, XQ,
                                    x_kv, kvn_g, kvn_b, XKV);

    // 3: fused Q+K+V projection (scale*log2e folded into Q)
    gemm_qkv<<<dim3(24, MROWS / 128), 256, GEMM_SMEM>>>(
        XQ, XKV, WQh, WKh, WVh, bq, bk, bv, Qb, Kb, Vb);

    // 4: tensor-core attention (ncu-profiled launch)
    attn_mma<<<dim3(NN / 64, HH, BB), 128, ATTN_SMEM>>>(Qb, Kb, Vb, ATT);

    // 5: out projection + residual with x_q
    gemm_mma<1><<<dim3(DQ / 128, MROWS / 128), 256, GEMM_SMEM>>>(
        ATT, WOh, bo, x_q, out, nullptr, DQ, DQ, 1.0f);

    // 6: LN2
    ln_kernel<<<MROWS, 256>>>(out, n2_g, n2_b, X2);

    // 7: MLP up + GELU -> fp16
    gemm_mma<2><<<dim3(DFF / 128, MROWS / 128), 256, GEMM_SMEM>>>(
        X2, W1h, b1, nullptr, nullptr, Hb, DFF, DQ, 1.0f);

    // 8: MLP down + residual accumulate into d_out
    gemm_mma<3><<<dim3(DQ / 128, MROWS / 128), 256, GEMM_SMEM>>>(
        Hb, W2h, b2, nullptr, out, nullptr, DQ, DFF, 1.0f);
}

// round 17
// speedup vs baseline: 1.0950x; 1.0179x over previous
#include <cuda_runtime.h>
#include <cuda_fp16.h>
#include <math.h>
#include <stdint.h>

#define BB   2
#define NN   2048
#define LL   2048
#define DQ   1024
#define HH   16
#define HD   64
#define MROWS 4096
#define DFF  4096
#define LOG2E 1.4426950408889634f

typedef __half hf;

// ---------------------------------------------------------------------------
// Static scratch (fp16), offsets in EM elements.
// ---------------------------------------------------------------------------
#define EM (1024u*1024u)
__device__ __align__(256) hf g_hf[60u * EM];

#define O_XQ  0
#define O_XKV 4
#define O_ATT 8
#define O_X2  12
#define O_H   16
#define O_WQ  32
#define O_WK  33
#define O_WV  34
#define O_WO  35
#define O_W1  36
#define O_W2  40
#define O_Q   44
#define O_K   48
#define O_V   52

// ---------------------------------------------------------------------------
// helpers
// ---------------------------------------------------------------------------
__device__ __forceinline__ uint32_t smem_u32(const void* p) {
    uint32_t a;
    asm("{ .reg .u64 t; cvta.to.shared.u64 t, %1; cvt.u32.u64 %0, t; }" : "=r"(a) : "l"(p));
    return a;
}
__device__ __forceinline__ void ldmx4(uint32_t& r0, uint32_t& r1, uint32_t& r2,
                                      uint32_t& r3, uint32_t a) {
    asm volatile("ldmatrix.sync.aligned.m8n8.x4.shared.b16 {%0,%1,%2,%3}, [%4];"
                 : "=r"(r0), "=r"(r1), "=r"(r2), "=r"(r3) : "r"(a));
}
__device__ __forceinline__ void ldmx4t(uint32_t& r0, uint32_t& r1, uint32_t& r2,
                                       uint32_t& r3, uint32_t a) {
    asm volatile("ldmatrix.sync.aligned.m8n8.x4.trans.shared.b16 {%0,%1,%2,%3}, [%4];"
                 : "=r"(r0), "=r"(r1), "=r"(r2), "=r"(r3) : "r"(a));
}
__device__ __forceinline__ void mma16816(float* d, const uint32_t* a,
                                         uint32_t b0, uint32_t b1) {
    asm volatile(
        "mma.sync.aligned.m16n8k16.row.col.f32.f16.f16.f32 "
        "{%0,%1,%2,%3}, {%4,%5,%6,%7}, {%8,%9}, {%0,%1,%2,%3};"
        : "+f"(d[0]), "+f"(d[1]), "+f"(d[2]), "+f"(d[3])
        : "r"(a[0]), "r"(a[1]), "r"(a[2]), "r"(a[3]), "r"(b0), "r"(b1));
}
__device__ __forceinline__ void cp16(uint32_t dst, const void* src) {
    asm volatile("cp.async.cg.shared.global [%0], [%1], 16;" :: "r"(dst), "l"(src));
}
#define CP_COMMIT() asm volatile("cp.async.commit_group;" ::: "memory")
#define CP_WAIT0()  asm volatile("cp.async.wait_group 0;" ::: "memory")
#define CP_WAIT1()  asm volatile("cp.async.wait_group 1;" ::: "memory")

__device__ __forceinline__ float gelu_exact(float x) {
    return 0.5f * x * (1.f + erff(x * 0.7071067811865476f));
}
__device__ __forceinline__ uint32_t pack2(float a, float b) {
    __half2 H = __halves2half2(__float2half_rn(a), __float2half_rn(b));
    return *(uint32_t*)&H;
}

// GEMM smem swizzle: pitch 64B, 16B chunk XORed with (row>>1)&3.
__device__ __forceinline__ uint32_t swz(uint32_t row, uint32_t colbyte) {
    return row * 64 + ((((colbyte >> 4) ^ (row >> 1)) & 3u) << 4);
}

// ---------------------------------------------------------------------------
// LN body (shared by fused + standalone kernels)
// ---------------------------------------------------------------------------
__device__ __forceinline__ void ln_body(const float* __restrict__ x,
                                        const float* __restrict__ g,
                                        const float* __restrict__ b,
                                        hf* __restrict__ y, int row) {
    const float* xr = x + (size_t)row * DQ;
    float v[4];
    float s = 0.f, s2 = 0.f;
#pragma unroll
    for (int i = 0; i < 4; i++) {
        float t = xr[threadIdx.x + i * 256];
        v[i] = t; s += t; s2 += t * t;
    }
#pragma unroll
    for (int o = 16; o > 0; o >>= 1) {
        s  += __shfl_xor_sync(0xffffffffu, s,  o);
        s2 += __shfl_xor_sync(0xffffffffu, s2, o);
    }
    __shared__ float ws[8], ws2[8];
    int w = threadIdx.x >> 5, lane = threadIdx.x & 31;
    if (lane == 0) { ws[w] = s; ws2[w] = s2; }
    __syncthreads();
    if (w == 0) {
        s  = (lane < 8) ? ws[lane]  : 0.f;
        s2 = (lane < 8) ? ws2[lane] : 0.f;
#pragma unroll
        for (int o = 4; o > 0; o >>= 1) {
            s  += __shfl_xor_sync(0xffffffffu, s,  o);
            s2 += __shfl_xor_sync(0xffffffffu, s2, o);
        }
        if (lane == 0) { ws[0] = s; ws2[0] = s2; }
    }
    __syncthreads();
    float mean = ws[0] * (1.f / DQ);
    float var  = ws2[0] * (1.f / DQ) - mean * mean;
    float rstd = rsqrtf(var + 1e-5f);
    size_t base = (size_t)row * DQ;
#pragma unroll
    for (int i = 0; i < 4; i++) {
        int c = threadIdx.x + i * 256;
        float yv = (v[i] - mean) * rstd * g[c] + b[c];
        y[base + c] = __float2half_rn(yv);
    }
}

// ---------------------------------------------------------------------------
// Fused prep kernel: blocks [0,12288) convert all 6 weights to fp16;
// blocks [12288, 12288+8192) do the two input LayerNorms.
// ---------------------------------------------------------------------------
#define CONV_BLKS 12288
__global__ void prep_kernel(
    const float* __restrict__ wq, const float* __restrict__ wk,
    const float* __restrict__ wv, const float* __restrict__ wo,
    const float* __restrict__ w1, const float* __restrict__ w2,
    hf* __restrict__ base,
    const float* __restrict__ xA, const float* __restrict__ gA,
    const float* __restrict__ bA, hf* __restrict__ yA,
    const float* __restrict__ xB, const float* __restrict__ gB,
    const float* __restrict__ bB, hf* __restrict__ yB) {
    if (blockIdx.x < CONV_BLKS) {
        int i = blockIdx.x * 256 + threadIdx.x;   // 0 .. 3M-1
        const float* w; hf* h; int off;
        if (i < (1 << 20)) {
            int seg = i >> 18;
            off = i & 0x3FFFF;
            w = seg == 0 ? wq : seg == 1 ? wk : seg == 2 ? wv : wo;
            h = base + (size_t)(O_WQ + seg) * EM;
        } else {
            int j = i - (1 << 20);
            int seg = j >> 20;
            off = j & 0xFFFFF;
            w = seg == 0 ? w1 : w2;
            h = base + (size_t)(seg == 0 ? O_W1 : O_W2) * EM;
        }
        float4 v = ((const float4*)w)[off];
        __half2* hp = (__half2*)(h + (size_t)off * 4);
        hp[0] = __halves2half2(__float2half_rn(v.x), __float2half_rn(v.y));
        hp[1] = __halves2half2(__float2half_rn(v.z), __float2half_rn(v.w));
    } else {
        int row = blockIdx.x - CONV_BLKS;
        if (row < MROWS) ln_body(xA, gA, bA, yA, row);
        else             ln_body(xB, gB, bB, yB, row - MROWS);
    }
}

// standalone LN (for LN2)
__global__ void ln_kernel(const float* __restrict__ x,
                          const float* __restrict__ g,
                          const float* __restrict__ b,
                          hf* __restrict__ y) {
    ln_body(x, g, b, y, blockIdx.x);
}

// ---------------------------------------------------------------------------
// HMMA GEMM core (R13/R16 config — unchanged).
// ---------------------------------------------------------------------------
#define MAT_BYTES (128 * 64)
#define STAGE_BYTES (2 * MAT_BYTES)
#define GEMM_SMEM (3 * STAGE_BYTES)

template <int EPI>
__device__ __forceinline__ void gemm_core(
    const hf* __restrict__ A, const hf* __restrict__ B,
    const float* __restrict__ bias, const float* __restrict__ res,
    float* __restrict__ C, hf* __restrict__ Ho,
    int N, int K, float alpha, size_t m0, size_t n0, char* smc) {
    const int tid = threadIdx.x, lane = tid & 31, wid = tid >> 5;
    const int wm = wid & 1, wn = wid >> 1;
    const uint32_t sbase = smem_u32(smc);

    const hf* gsrc0 = A + m0 * K;
    const hf* gsrc1 = B + n0 * K;

    auto load_stage = [&](int s, int kt) {
        uint32_t base = sbase + s * STAGE_BYTES;
#pragma unroll
        for (int i = 0; i < 4; i++) {
            const int t = i >> 1;
            int idx = tid + (i & 1) * 256;
            int row = idx >> 2, seg = idx & 3;
            const hf* src = (t == 0 ? gsrc0 : gsrc1);
            cp16(base + t * MAT_BYTES + swz((uint32_t)row, (uint32_t)(seg * 16)),
                 src + (size_t)row * K + kt + seg * 8);
        }
    };

    float acc[4][4][4];
#pragma unroll
    for (int a = 0; a < 4; a++)
#pragma unroll
        for (int b = 0; b < 4; b++)
#pragma unroll
            for (int c = 0; c < 4; c++) acc[a][b][c] = 0.f;

    const int nk = K >> 5;
    load_stage(0, 0);
    CP_COMMIT();
    load_stage(1, 32);
    CP_COMMIT();

    const uint32_t brow = (uint32_t)(wn * 32 + ((lane >> 4) & 1) * 8 + (lane & 7));
    const uint32_t bcolh = (uint32_t)(((lane >> 3) & 1) * 16);
    const uint32_t arow = (uint32_t)(wm * 64 + (lane & 15));
    const uint32_t acolh = (uint32_t)((lane >> 4) * 16);

    int stage = 0;
    for (int cc = 0; cc < nk; cc++) {
        if (cc + 1 < nk) CP_WAIT1(); else CP_WAIT0();
        __syncthreads();
        if (cc + 2 < nk) {
            int ns = stage + 2; if (ns >= 3) ns -= 3;
            load_stage(ns, (cc + 2) << 5);
            CP_COMMIT();
        }

        uint32_t st = sbase + stage * STAGE_BYTES;
        uint32_t sA = st, sB = st + MAT_BYTES;

        uint32_t Bv[2][8];
#pragma unroll
        for (int k16 = 0; k16 < 2; k16++) {
            uint32_t bcol = (uint32_t)(k16 * 32) + bcolh;
#pragma unroll
            for (int pr = 0; pr < 2; pr++) {
                uint32_t bo = swz(brow + pr * 16, bcol);
                ldmx4(Bv[k16][pr * 4 + 0], Bv[k16][pr * 4 + 1],
                      Bv[k16][pr * 4 + 2], Bv[k16][pr * 4 + 3], sB + bo);
            }
        }

#pragma unroll
        for (int mt = 0; mt < 4; mt++) {
#pragma unroll
            for (int k16 = 0; k16 < 2; k16++) {
                uint32_t ao = swz(arow + mt * 16, (uint32_t)(k16 * 32) + acolh);
                uint32_t av[4];
                ldmx4(av[0], av[1], av[2], av[3], sA + ao);
#pragma unroll
                for (int nt = 0; nt < 4; nt++)
                    mma16816(acc[mt][nt], av, Bv[k16][nt * 2], Bv[k16][nt * 2 + 1]);
            }
        }
        stage++; if (stage >= 3) stage -= 3;
    }

#pragma unroll
    for (int mt = 0; mt < 4; mt++) {
        int r0 = wm * 64 + mt * 16 + (lane >> 2);
#pragma unroll
        for (int nt = 0; nt < 4; nt++) {
            size_t gcol = n0 + wn * 32 + nt * 8 + (lane & 3) * 2;
            float2 bb = *(const float2*)(bias + gcol);
#pragma unroll
            for (int h = 0; h < 2; h++) {
                size_t grow = m0 + r0 + h * 8;
                size_t idx = grow * (size_t)N + gcol;
                float v0 = acc[mt][nt][h * 2 + 0] + bb.x;
                float v1 = acc[mt][nt][h * 2 + 1] + bb.y;
                if (EPI == 1) {
                    float2 rr = *(const float2*)(res + idx);
                    v0 += rr.x; v1 += rr.y;
                }
                if (EPI == 3) {
                    float2 rr = *(const float2*)(C + idx);
                    v0 += rr.x; v1 += rr.y;
                }
                if (EPI == 2) {
                    v0 = gelu_exact(v0); v1 = gelu_exact(v1);
                    *(__half2*)(Ho + idx) =
                        __halves2half2(__float2half_rn(v0), __float2half_rn(v1));
                } else if (EPI == 5) {
                    v0 *= alpha; v1 *= alpha;
                    *(__half2*)(Ho + idx) =
                        __halves2half2(__float2half_rn(v0), __float2half_rn(v1));
                } else {
                    float2 o; o.x = v0; o.y = v1;
                    *(float2*)(C + idx) = o;
                }
            }
        }
    }
}

template <int EPI>
__global__ void __launch_bounds__(256, 2)
gemm_mma(const hf* __restrict__ A, const hf* __restrict__ B,
         const float* __restrict__ bias, const float* __restrict__ res,
         float* __restrict__ C, hf* __restrict__ Ho,
         int N, int K, float alpha) {
    extern __shared__ char smc[];
    gemm_core<EPI>(A, B, bias, res, C, Ho, N, K, alpha,
                   (size_t)blockIdx.y * 128, (size_t)blockIdx.x * 128, smc);
}

// Fused Q/K/V projection
__global__ void __launch_bounds__(256, 2)
gemm_qkv(const hf* __restrict__ XQ, const hf* __restrict__ XKV,
         const hf* __restrict__ WQ, const hf* __restrict__ WK,
         const hf* __restrict__ WV,
         const float* __restrict__ bq, const float* __restrict__ bk,
         const float* __restrict__ bv,
         hf* __restrict__ Q, hf* __restrict__ K, hf* __restrict__ V) {
    extern __shared__ char smc[];
    size_t m0 = (size_t)blockIdx.y * 128;
    int xb = blockIdx.x;
    if (xb < 8) {
        gemm_core<5>(XQ, WQ, bq, nullptr, nullptr, Q,
                     DQ, DQ, 0.125f * LOG2E, m0, (size_t)xb * 128, smc);
    } else if (xb < 16) {
        gemm_core<5>(XKV, WK, bk, nullptr, nullptr, K,
                     DQ, DQ, 1.0f, m0, (size_t)(xb - 8) * 128, smc);
    } else {
        gemm_core<5>(XKV, WV, bv, nullptr, nullptr, V,
                     DQ, DQ, 1.0f, m0, (size_t)(xb - 16) * 128, smc);
    }
}

// ---------------------------------------------------------------------------
// Tensor-core flash attention, softmax-1 (log2 domain), x4 ldmatrix loads.
// 128 threads x 64 q-rows, 4 CTAs/SM.
// ---------------------------------------------------------------------------
#define APB 144
#define KV_MAT (64 * APB)
#define KV_STAGE (2 * KV_MAT)
#define ATTN_SMEM (2 * KV_STAGE)

__global__ void __launch_bounds__(128, 4)
attn_mma(const hf* __restrict__ Qp, const hf* __restrict__ Kp,
         const hf* __restrict__ Vp, hf* __restrict__ Op) {
    extern __shared__ char smc[];
    const uint32_t sb = smem_u32(smc);
    const int tid = threadIdx.x, lane = tid & 31, wid = tid >> 5;
    const int b = blockIdx.z, h = blockIdx.y;
    const int n0 = blockIdx.x * 64;
    const size_t qrow0 = (size_t)b * NN + n0;
    const size_t col0 = (size_t)h * HD;

    {
        const hf* s0 = Qp + qrow0 * DQ + col0;
#pragma unroll
        for (int it = 0; it < 4; it++) {
            int g = it * 128 + tid;
            int r = g >> 3, c = g & 7;
            cp16(sb + r * APB + c * 16, s0 + (size_t)r * DQ + c * 8);
        }
    }
    CP_COMMIT();
    CP_WAIT0();
    __syncthreads();

    uint32_t qv[4][4];
#pragma unroll
    for (int k16 = 0; k16 < 4; k16++) {
        uint32_t ao = (uint32_t)(wid * 16 + (lane & 15)) * APB
                    + (uint32_t)(k16 * 16 + (lane >> 4) * 8) * 2;
        ldmx4(qv[k16][0], qv[k16][1], qv[k16][2], qv[k16][3], sb + ao);
    }
    __syncthreads();

    const hf* ksrc = Kp + ((size_t)b * LL) * DQ + col0;
    const hf* vsrc = Vp + ((size_t)b * LL) * DQ + col0;
    auto load_kv = [&](int blk, int s) {
        uint32_t base = sb + s * KV_STAGE;
        size_t roff = (size_t)blk * 64;
#pragma unroll
        for (int it = 0; it < 8; it++) {
            int g = it * 128 + tid;
            int m = g >> 9;
            int r = (g & 511) >> 3, c = g & 7;
            const hf* src = m == 0 ? ksrc : vsrc;
            cp16(base + m * KV_MAT + r * APB + c * 16,
                 src + (roff + r) * DQ + c * 8);
        }
    };

    float m_[2] = {0.f, 0.f}, l_[2] = {1.f, 1.f};
    float o_[8][4];
#pragma unroll
    for (int d = 0; d < 8; d++)
#pragma unroll
        for (int j = 0; j < 4; j++) o_[d][j] = 0.f;

    load_kv(0, 0);
    CP_COMMIT();

    // hoisted lane-dependent offsets
    // K (x4): matrices (nt_even klo, nt_even khi, nt_odd klo, nt_odd khi)
    const uint32_t krow_off = (uint32_t)(((lane >> 4) & 1) * 8 + (lane & 7));
    const uint32_t kcol_off = (uint32_t)(((lane >> 3) & 1) * 16);
    // V (x4 trans): matrices (dt_even b0, dt_even b1, dt_odd b0, dt_odd b1)
    const uint32_t vrow_off = (uint32_t)(lane & 15);
    const uint32_t vcol_off = (uint32_t)(((lane >> 4) & 1) * 16);

    const int NBLK = LL / 64;
    for (int i = 0; i < NBLK; i++) {
        if (i + 1 < NBLK) { load_kv(i + 1, (i + 1) & 1); CP_COMMIT(); CP_WAIT1(); }
        else CP_WAIT0();
        __syncthreads();

        uint32_t stg = sb + (i & 1) * KV_STAGE;

        float s_[8][4];
#pragma unroll
        for (int nt = 0; nt < 8; nt++)
#pragma unroll
            for (int j = 0; j < 4; j++) s_[nt][j] = 0.f;

        // ---- S = Q K^T : x4 loads, 4 ldmx4 per k16 ----
#pragma unroll
        for (int k16 = 0; k16 < 4; k16++) {
            uint32_t bcol = (uint32_t)(k16 * 32) + kcol_off;
#pragma unroll
            for (int ntp = 0; ntp < 4; ntp++) {
                uint32_t bo = (krow_off + ntp * 16) * APB + bcol;
                uint32_t r0, r1, r2, r3;
                ldmx4(r0, r1, r2, r3, stg + bo);
                mma16816(s_[2 * ntp + 0], qv[k16], r0, r1);
                mma16816(s_[2 * ntp + 1], qv[k16], r2, r3);
            }
        }

#pragma unroll
        for (int hh = 0; hh < 2; hh++) {
            float mx = s_[0][hh * 2];
#pragma unroll
            for (int nt = 0; nt < 8; nt++)
                mx = fmaxf(mx, fmaxf(s_[nt][hh * 2], s_[nt][hh * 2 + 1]));
            mx = fmaxf(mx, __shfl_xor_sync(0xffffffffu, mx, 1));
            mx = fmaxf(mx, __shfl_xor_sync(0xffffffffu, mx, 2));
            float mn = fmaxf(m_[hh], mx);
            float corr = exp2f(m_[hh] - mn);
            m_[hh] = mn;
            float sum = 0.f;
#pragma unroll
            for (int nt = 0; nt < 8; nt++) {
                float p0 = exp2f(s_[nt][hh * 2] - mn);
                float p1 = exp2f(s_[nt][hh * 2 + 1] - mn);
                s_[nt][hh * 2] = p0; s_[nt][hh * 2 + 1] = p1;
                sum += p0 + p1;
            }
            sum += __shfl_xor_sync(0xffffffffu, sum, 1);
            sum += __shfl_xor_sync(0xffffffffu, sum, 2);
            l_[hh] = l_[hh] * corr + sum;
#pragma unroll
            for (int d = 0; d < 8; d++) {
                o_[d][hh * 2] *= corr; o_[d][hh * 2 + 1] *= corr;
            }
        }

        uint32_t ph[4][4];
#pragma unroll
        for (int j = 0; j < 4; j++) {
            ph[j][0] = pack2(s_[2 * j][0], s_[2 * j][1]);
            ph[j][1] = pack2(s_[2 * j][2], s_[2 * j][3]);
            ph[j][2] = pack2(s_[2 * j + 1][0], s_[2 * j + 1][1]);
            ph[j][3] = pack2(s_[2 * j + 1][2], s_[2 * j + 1][3]);
        }

        // ---- O += P V : x4 trans loads, 4 ldmx4t per j ----
        uint32_t vbase = stg + KV_MAT;
#pragma unroll
        for (int j = 0; j < 4; j++) {
            uint32_t vrow = (uint32_t)(j * 16) + vrow_off;
#pragma unroll
            for (int dtp = 0; dtp < 4; dtp++) {
                uint32_t vo = vrow * APB + dtp * 32 + vcol_off;
                uint32_t r0, r1, r2, r3;
                ldmx4t(r0, r1, r2, r3, vbase + vo);
                mma16816(o_[2 * dtp + 0], ph[j], r0, r1);
                mma16816(o_[2 * dtp + 1], ph[j], r2, r3);
            }
        }
        __syncthreads();
    }

    float inv0 = 1.f / l_[0], inv1 = 1.f / l_[1];
#pragma unroll
    for (int hh = 0; hh < 2; hh++) {
        float inv = hh == 0 ? inv0 : inv1;
        size_t grow = qrow0 + wid * 16 + (lane >> 2) + hh * 8;
#pragma unroll
        for (int dt = 0; dt < 8; dt++) {
            size_t idx = grow * DQ + col0 + dt * 8 + (lane & 3) * 2;
            *(__half2*)(Op + idx) =
                __halves2half2(__float2half_rn(o_[dt][hh * 2] * inv),
                               __float2half_rn(o_[dt][hh * 2 + 1] * inv));
        }
    }
}

// ---------------------------------------------------------------------------
// kernel_launch
// ---------------------------------------------------------------------------
extern "C" void kernel_launch(void* const* d_in, const int* in_sizes, int n_in,
                              void* d_out, int out_size) {
    const float* x_q   = (const float*)d_in[0];
    const float* x_kv  = (const float*)d_in[1];
    const float* qn_g  = (const float*)d_in[2];
    const float* qn_b  = (const float*)d_in[3];
    const float* kvn_g = (const float*)d_in[4];
    const float* kvn_b = (const float*)d_in[5];
    const float* Wq    = (const float*)d_in[6];
    const float* bq    = (const float*)d_in[7];
    const float* Wk    = (const float*)d_in[8];
    const float* bk    = (const float*)d_in[9];
    const float* Wv    = (const float*)d_in[10];
    const float* bv    = (const float*)d_in[11];
    const float* Wo    = (const float*)d_in[12];
    const float* bo    = (const float*)d_in[13];
    const float* n2_g  = (const float*)d_in[14];
    const float* n2_b  = (const float*)d_in[15];
    const float* W1    = (const float*)d_in[16];
    const float* b1    = (const float*)d_in[17];
    const float* W2    = (const float*)d_in[18];
    const float* b2    = (const float*)d_in[19];
    float* out = (float*)d_out;

    hf* hb = nullptr;
    cudaGetSymbolAddress((void**)&hb, g_hf);

    hf* XQ  = hb + (size_t)O_XQ * EM;
    hf* XKV = hb + (size_t)O_XKV * EM;
    hf* ATT = hb + (size_t)O_ATT * EM;
    hf* X2  = hb + (size_t)O_X2 * EM;
    hf* Hb  = hb + (size_t)O_H * EM;
    hf* WQh = hb + (size_t)O_WQ * EM;
    hf* WKh = hb + (size_t)O_WK * EM;
    hf* WVh = hb + (size_t)O_WV * EM;
    hf* WOh = hb + (size_t)O_WO * EM;
    hf* W1h = hb + (size_t)O_W1 * EM;
    hf* W2h = hb + (size_t)O_W2 * EM;
    hf* Qb  = hb + (size_t)O_Q * EM;
    hf* Kb  = hb + (size_t)O_K * EM;
    hf* Vb  = hb + (size_t)O_V * EM;

    cudaFuncSetAttribute(gemm_mma<1>, cudaFuncAttributeMaxDynamicSharedMemorySize, GEMM_SMEM);
    cudaFuncSetAttribute(gemm_mma<2>, cudaFuncAttributeMaxDynamicSharedMemorySize, GEMM_SMEM);
    cudaFuncSetAttribute(gemm_mma<3>, cudaFuncAttributeMaxDynamicSharedMemorySize, GEMM_SMEM);
    cudaFuncSetAttribute(gemm_qkv, cudaFuncAttributeMaxDynamicSharedMemorySize, GEMM_SMEM);
    cudaFuncSetAttribute(attn_mma, cudaFuncAttributeMaxDynamicSharedMemorySize, ATTN_SMEM);

    // 1: weight converts + both input LNs fused into one launch
    prep_kernel<<<CONV_BLKS + 2 * MROWS, 256>>>(
        Wq, Wk, Wv, Wo, W1, W2, hb,
        x_q, qn_g, qn_b, XQ, x_kv, kvn_g, kvn_b, XKV);

    // 2: fused Q+K+V projection (scale*log2e folded into Q)
    gemm_qkv<<<dim3(24, MROWS / 128), 256, GEMM_SMEM>>>(
        XQ, XKV, WQh, WKh, WVh, bq, bk, bv, Qb, Kb, Vb);

    // 3: tensor-core attention
    attn_mma<<<dim3(NN / 64, HH, BB), 128, ATTN_SMEM>>>(Qb, Kb, Vb, ATT);

    // 4: out projection + residual with x_q
    gemm_mma<1><<<dim3(DQ / 128, MROWS / 128), 256, GEMM_SMEM>>>(
        ATT, WOh, bo, x_q, out, nullptr, DQ, DQ, 1.0f);

    // 5: LN2
    ln_kernel<<<MROWS, 256>>>(out, n2_g, n2_b, X2);

    // 6: MLP up + GELU -> fp16
    gemm_mma<2><<<dim3(DFF / 128, MROWS / 128), 256, GEMM_SMEM>>>(
        X2, W1h, b1, nullptr, nullptr, Hb, DFF, DQ, 1.0f);

    // 7: MLP down + residual accumulate into d_out
    gemm_mma<3><<<dim3(DQ / 128, MROWS / 128), 256, GEMM_SMEM>>>(
        Hb, W2h, b2, nullptr, out, nullptr, DQ, DFF, 1.0f);
}